// round 5
// baseline (speedup 1.0000x reference)
#include <cuda_runtime.h>
#include <cuda_bf16.h>
#include <math_constants.h>

// Problem constants
#define BATCH 2
#define T_LEN 4096
#define C_DIM 1024
#define NH 16
#define HS 64
#define BD 16
#define DELTA 32

// ---------------------------------------------------------------------------
// Scratch (no allocations allowed)
// ---------------------------------------------------------------------------
__device__ float g_disp[BATCH * T_LEN * (NH * BD)];   // (B,T,256)
__device__ float g_val [BATCH * T_LEN * C_DIM];       // (B,T,1024)
__device__ float g_attn[BATCH * T_LEN * C_DIM];       // (B,T,1024)
__device__ float g_posf[DELTA * BD];                  // (32,16)

// ---------------------------------------------------------------------------
// pos_feat = rel_pos_emb (32,16) @ W_pos (16,16)
// ---------------------------------------------------------------------------
__global__ void posfeat_kernel(const float* __restrict__ rpe,
                               const float* __restrict__ Wpos,
                               float* __restrict__ out)
{
    int i = threadIdx.x;           // 512 threads, one output each
    if (i >= DELTA * BD) return;
    int d = i / BD, k = i % BD;
    float a = 0.f;
    for (int q = 0; q < BD; q++) a += rpe[d * BD + q] * Wpos[q * BD + k];
    out[i] = a;
}

// ---------------------------------------------------------------------------
// Simple, trivially-verifiable tiled GEMM: C[M,N] = A[M,K] @ B[K,N]
// 16x16 tile, one output element per thread. All dims % 16 == 0 here.
// ---------------------------------------------------------------------------
#define TS 16
__global__ void gemm_simple(const float* __restrict__ A,
                            const float* __restrict__ B,
                            float* __restrict__ C, int M, int N, int K)
{
    __shared__ float As[TS][TS];
    __shared__ float Bs[TS][TS];

    const int row = blockIdx.y * TS + threadIdx.y;
    const int col = blockIdx.x * TS + threadIdx.x;

    float acc = 0.f;
    for (int k0 = 0; k0 < K; k0 += TS) {
        As[threadIdx.y][threadIdx.x] = A[(size_t)row * K + k0 + threadIdx.x];
        Bs[threadIdx.y][threadIdx.x] = B[(size_t)(k0 + threadIdx.y) * N + col];
        __syncthreads();
        for (int kk = 0; kk < TS; kk++)
            acc += As[threadIdx.y][kk] * Bs[kk][threadIdx.x];
        __syncthreads();
    }
    C[(size_t)row * N + col] = acc;
}

// ---------------------------------------------------------------------------
// Literal windowed attention: one thread per (b, n, t).
// Mirrors the reference computation statement-by-statement.
// ---------------------------------------------------------------------------
__device__ __forceinline__ float gelu_ref(float x) {
    // jax.nn.gelu(approximate=False) = 0.5 * x * (1 + erf(x / sqrt(2)))
    return 0.5f * x * (1.f + erff(x * 0.7071067811865476f));
}

__global__ void attn_naive(
    const float* __restrict__ disp,   // (B,T,256), channel = n*BD + i
    const float* __restrict__ val,    // (B,T,1024), channel = n*HS + h
    const float* __restrict__ Wsf,    // (16,32) row-major
    const float* __restrict__ bsf,    // (32)
    const float* __restrict__ wbond,  // (16)
    const float* __restrict__ wdmg,   // (16)
    const float* __restrict__ bdmg,   // scalar
    const float* __restrict__ posf,   // (32,16) row-major [d][k]
    float* __restrict__ attn)         // (B,T,1024), channel = n*HS + h
{
    const int g = blockIdx.x * blockDim.x + threadIdx.x;   // (b*NH+n)*T + t
    if (g >= BATCH * NH * T_LEN) return;
    const int t  = g % T_LEN;
    const int bn = g / T_LEN;
    const int b  = bn / NH, n = bn % NH;

    // center = disp[b, n, t, :]
    float center[BD];
    for (int i = 0; i < BD; i++)
        center[i] = disp[((size_t)b * T_LEN + t) * 256 + n * BD + i];

    const float bdm = bdmg[0];

    float score[DELTA];
    for (int d = 0; d < DELTA; d++) {
        const int j = t + d - (DELTA - 1);
        float strain[BD];
        if (j >= 0) {
            for (int i = 0; i < BD; i++)
                strain[i] = disp[((size_t)b * T_LEN + j) * 256 + n * BD + i] - center[i];
        } else {
            for (int i = 0; i < BD; i++) strain[i] = -center[i];
        }

        // bond branch: gelu(strain @ Wsf[:, :16] + bsf[:16] + posf[d, :]) . wbond
        float bond = 0.f;
        for (int k = 0; k < BD; k++) {
            float f = bsf[k];
            for (int i = 0; i < BD; i++) f += strain[i] * Wsf[i * 32 + k];
            f += posf[d * BD + k];
            bond += gelu_ref(f) * wbond[k];
        }
        // damage branch: sigmoid(gelu(strain @ Wsf[:, 16:] + bsf[16:]) . wdmg + bdmg)
        float dz = 0.f;
        for (int k = 0; k < BD; k++) {
            float f = bsf[BD + k];
            for (int i = 0; i < BD; i++) f += strain[i] * Wsf[i * 32 + BD + k];
            dz += gelu_ref(f) * wdmg[k];
        }
        const float damage = 1.f / (1.f + expf(-(dz + bdm)));

        score[d] = (j >= 0) ? (bond - 10.f * damage) : -CUDART_INF_F;
    }

    // softmax over d
    float m = -CUDART_INF_F;
    for (int d = 0; d < DELTA; d++) m = fmaxf(m, score[d]);
    float ssum = 0.f;
    for (int d = 0; d < DELTA; d++) { score[d] = expf(score[d] - m); ssum += score[d]; }
    const float inv = 1.f / ssum;
    for (int d = 0; d < DELTA; d++) score[d] *= inv;

    // out[h] = sum_d w[d] * val[b, t+d-31, n*HS+h]
    float* orow = attn + ((size_t)b * T_LEN + t) * C_DIM + n * HS;
    for (int h = 0; h < HS; h++) {
        float acc = 0.f;
        for (int d = 0; d < DELTA; d++) {
            const int j = t + d - (DELTA - 1);
            if (j >= 0)
                acc += score[d] * val[((size_t)b * T_LEN + j) * C_DIM + n * HS + h];
        }
        orow[h] = acc;
    }
}

// ---------------------------------------------------------------------------
// Launch
// ---------------------------------------------------------------------------
extern "C" void kernel_launch(void* const* d_in, const int* in_sizes, int n_in,
                              void* d_out, int out_size)
{
    static const int sigA[11] = {8388608, 262144, 1048576, 512, 256, 512, 32, 16, 16, 1, 1048576};

    const float *x = 0, *Wdisp = 0, *Wval = 0, *rpe = 0, *Wpos = 0, *Wsf = 0,
                *bsf = 0, *wbond = 0, *wdmg = 0, *bdmg = 0, *Wcproj = 0;

    bool mA = (n_in == 11);
    for (int i = 0; i < 11 && i < n_in; i++) if (in_sizes[i] != sigA[i]) mA = false;

    if (mA) {
        x      = (const float*)d_in[0];  Wdisp  = (const float*)d_in[1];
        Wval   = (const float*)d_in[2];  rpe    = (const float*)d_in[3];
        Wpos   = (const float*)d_in[4];  Wsf    = (const float*)d_in[5];
        bsf    = (const float*)d_in[6];  wbond  = (const float*)d_in[7];
        wdmg   = (const float*)d_in[8];  bdmg   = (const float*)d_in[9];
        Wcproj = (const float*)d_in[10];
    } else {
        int seen1M = 0, seen512 = 0, seen16 = 0;
        for (int i = 0; i < n_in; i++) {
            const float* p = (const float*)d_in[i];
            switch (in_sizes[i]) {
                case 8388608: x = p; break;
                case 262144:  Wdisp = p; break;
                case 256:     Wpos = p; break;
                case 32:      bsf = p; break;
                case 1:       bdmg = p; break;
                case 1048576: if (seen1M++ == 0) Wval = p; else Wcproj = p; break;
                case 512:     if (seen512++ == 0) rpe = p; else Wsf = p; break;
                case 16:      if (seen16++ == 0) wbond = p; else wdmg = p; break;
                default: break;
            }
        }
    }
    float* out = (float*)d_out;

    float *p_disp, *p_val, *p_attn, *p_posf;
    cudaGetSymbolAddress((void**)&p_disp, g_disp);
    cudaGetSymbolAddress((void**)&p_val,  g_val);
    cudaGetSymbolAddress((void**)&p_attn, g_attn);
    cudaGetSymbolAddress((void**)&p_posf, g_posf);

    const int M = BATCH * T_LEN;   // 8192

    posfeat_kernel<<<1, 512>>>(rpe, Wpos, p_posf);

    // disp = x @ W_disp  (8192 x 256, K=1024)
    {
        dim3 blk(TS, TS);
        dim3 grid((NH * BD) / TS, M / TS);
        gemm_simple<<<grid, blk>>>(x, Wdisp, p_disp, M, NH * BD, C_DIM);
    }
    // val = x @ W_val    (8192 x 1024, K=1024)
    {
        dim3 blk(TS, TS);
        dim3 grid(C_DIM / TS, M / TS);
        gemm_simple<<<grid, blk>>>(x, Wval, p_val, M, C_DIM, C_DIM);
    }
    // windowed attention -> (B,T,C)
    {
        const int total = BATCH * NH * T_LEN;   // 131072
        attn_naive<<<(total + 255) / 256, 256>>>(p_disp, p_val, Wsf, bsf,
                                                 wbond, wdmg, bdmg, p_posf, p_attn);
    }
    // out = attn @ W_cproj (8192 x 1024, K=1024)
    {
        dim3 blk(TS, TS);
        dim3 grid(C_DIM / TS, M / TS);
        gemm_simple<<<grid, blk>>>(p_attn, Wcproj, out, M, C_DIM, C_DIM);
    }
}

// round 6
// speedup vs baseline: 1.3561x; 1.3561x over previous
#include <cuda_runtime.h>
#include <cuda_bf16.h>
#include <math_constants.h>

// Problem constants
#define BATCH 2
#define T_LEN 4096
#define C_DIM 1024
#define NH 16
#define HS 64
#define BD 16
#define DELTA 32

// ---------------------------------------------------------------------------
// Scratch (no allocations allowed)
// ---------------------------------------------------------------------------
__device__ float g_disp[BATCH * T_LEN * (NH * BD)];   // (B,T,256)
__device__ float g_val [BATCH * T_LEN * C_DIM];       // (B,T,1024)
__device__ float g_attn[BATCH * T_LEN * C_DIM];       // (B,T,1024)
__device__ float g_posf[DELTA * BD];                  // (32,16)

// ---------------------------------------------------------------------------
// pos_feat = rel_pos_emb (32,16) @ W_pos (16,16)
// ---------------------------------------------------------------------------
__global__ void posfeat_kernel(const float* __restrict__ rpe,
                               const float* __restrict__ Wpos,
                               float* __restrict__ out)
{
    int i = threadIdx.x;           // 512 threads, one output each
    if (i >= DELTA * BD) return;
    int d = i / BD, k = i % BD;
    float a = 0.f;
    for (int q = 0; q < BD; q++) a += rpe[d * BD + q] * Wpos[q * BD + k];
    out[i] = a;
}

// ---------------------------------------------------------------------------
// Fresh register-tiled SGEMM: C[M,N] = A[M,K] @ B[K,N]
// Block tile 128x128, K-tile 8, 256 threads, each thread computes 8x8.
// Loaders are simple strided scalar loops (1024 elements, 256 threads, 4 each).
// Requires M%128==0, N%128==0, K%8==0 (true for all GEMMs here).
// ---------------------------------------------------------------------------
__global__ void __launch_bounds__(256) sgemm128(
    const float* __restrict__ A, const float* __restrict__ B,
    float* __restrict__ C, int M, int N, int K)
{
    __shared__ float As[8][128];   // As[kk][m]
    __shared__ float Bs[8][128];   // Bs[kk][n]

    const int tid = threadIdx.x;          // 0..255
    const int bm  = blockIdx.y * 128;     // block row origin
    const int bn  = blockIdx.x * 128;     // block col origin

    // thread's 8x8 patch: rows tm..tm+7, cols tn..tn+7 (within tile)
    const int tm = (tid / 16) * 8;        // 0,8,...,120
    const int tn = (tid % 16) * 8;        // 0,8,...,120

    float acc[8][8];
    for (int i = 0; i < 8; i++)
        for (int j = 0; j < 8; j++) acc[i][j] = 0.f;

    for (int k0 = 0; k0 < K; k0 += 8) {
        // Load A tile: element (r, kk) of the 128x8 tile -> As[kk][r]
        // l runs over 1024 = 128*8 elements; r = l/8, kk = l%8.
        for (int l = tid; l < 128 * 8; l += 256) {
            int r  = l / 8;
            int kk = l % 8;
            As[kk][r] = A[(size_t)(bm + r) * K + (k0 + kk)];
        }
        // Load B tile: element (kk, n) of the 8x128 tile -> Bs[kk][n]
        // l runs over 1024; kk = l/128, nn = l%128. Coalesced over nn.
        for (int l = tid; l < 8 * 128; l += 256) {
            int kk = l / 128;
            int nn = l % 128;
            Bs[kk][nn] = B[(size_t)(k0 + kk) * N + (bn + nn)];
        }
        __syncthreads();

        for (int kk = 0; kk < 8; kk++) {
            float a[8], b[8];
            for (int i = 0; i < 8; i++) a[i] = As[kk][tm + i];
            for (int j = 0; j < 8; j++) b[j] = Bs[kk][tn + j];
            for (int i = 0; i < 8; i++)
                for (int j = 0; j < 8; j++)
                    acc[i][j] = fmaf(a[i], b[j], acc[i][j]);
        }
        __syncthreads();
    }

    for (int i = 0; i < 8; i++)
        for (int j = 0; j < 8; j++)
            C[(size_t)(bm + tm + i) * N + (bn + tn + j)] = acc[i][j];
}

// ---------------------------------------------------------------------------
// Literal windowed attention: one thread per (b, n, t).
// (UNCHANGED from the passing round-5 version.)
// ---------------------------------------------------------------------------
__device__ __forceinline__ float gelu_ref(float x) {
    // jax.nn.gelu(approximate=False) = 0.5 * x * (1 + erf(x / sqrt(2)))
    return 0.5f * x * (1.f + erff(x * 0.7071067811865476f));
}

__global__ void attn_naive(
    const float* __restrict__ disp,   // (B,T,256), channel = n*BD + i
    const float* __restrict__ val,    // (B,T,1024), channel = n*HS + h
    const float* __restrict__ Wsf,    // (16,32) row-major
    const float* __restrict__ bsf,    // (32)
    const float* __restrict__ wbond,  // (16)
    const float* __restrict__ wdmg,   // (16)
    const float* __restrict__ bdmg,   // scalar
    const float* __restrict__ posf,   // (32,16) row-major [d][k]
    float* __restrict__ attn)         // (B,T,1024), channel = n*HS + h
{
    const int g = blockIdx.x * blockDim.x + threadIdx.x;   // (b*NH+n)*T + t
    if (g >= BATCH * NH * T_LEN) return;
    const int t  = g % T_LEN;
    const int bn = g / T_LEN;
    const int b  = bn / NH, n = bn % NH;

    // center = disp[b, n, t, :]
    float center[BD];
    for (int i = 0; i < BD; i++)
        center[i] = disp[((size_t)b * T_LEN + t) * 256 + n * BD + i];

    const float bdm = bdmg[0];

    float score[DELTA];
    for (int d = 0; d < DELTA; d++) {
        const int j = t + d - (DELTA - 1);
        float strain[BD];
        if (j >= 0) {
            for (int i = 0; i < BD; i++)
                strain[i] = disp[((size_t)b * T_LEN + j) * 256 + n * BD + i] - center[i];
        } else {
            for (int i = 0; i < BD; i++) strain[i] = -center[i];
        }

        // bond branch: gelu(strain @ Wsf[:, :16] + bsf[:16] + posf[d, :]) . wbond
        float bond = 0.f;
        for (int k = 0; k < BD; k++) {
            float f = bsf[k];
            for (int i = 0; i < BD; i++) f += strain[i] * Wsf[i * 32 + k];
            f += posf[d * BD + k];
            bond += gelu_ref(f) * wbond[k];
        }
        // damage branch: sigmoid(gelu(strain @ Wsf[:, 16:] + bsf[16:]) . wdmg + bdmg)
        float dz = 0.f;
        for (int k = 0; k < BD; k++) {
            float f = bsf[BD + k];
            for (int i = 0; i < BD; i++) f += strain[i] * Wsf[i * 32 + BD + k];
            dz += gelu_ref(f) * wdmg[k];
        }
        const float damage = 1.f / (1.f + expf(-(dz + bdm)));

        score[d] = (j >= 0) ? (bond - 10.f * damage) : -CUDART_INF_F;
    }

    // softmax over d
    float m = -CUDART_INF_F;
    for (int d = 0; d < DELTA; d++) m = fmaxf(m, score[d]);
    float ssum = 0.f;
    for (int d = 0; d < DELTA; d++) { score[d] = expf(score[d] - m); ssum += score[d]; }
    const float inv = 1.f / ssum;
    for (int d = 0; d < DELTA; d++) score[d] *= inv;

    // out[h] = sum_d w[d] * val[b, t+d-31, n*HS+h]
    float* orow = attn + ((size_t)b * T_LEN + t) * C_DIM + n * HS;
    for (int h = 0; h < HS; h++) {
        float acc = 0.f;
        for (int d = 0; d < DELTA; d++) {
            const int j = t + d - (DELTA - 1);
            if (j >= 0)
                acc += score[d] * val[((size_t)b * T_LEN + j) * C_DIM + n * HS + h];
        }
        orow[h] = acc;
    }
}

// ---------------------------------------------------------------------------
// Launch
// ---------------------------------------------------------------------------
extern "C" void kernel_launch(void* const* d_in, const int* in_sizes, int n_in,
                              void* d_out, int out_size)
{
    static const int sigA[11] = {8388608, 262144, 1048576, 512, 256, 512, 32, 16, 16, 1, 1048576};

    const float *x = 0, *Wdisp = 0, *Wval = 0, *rpe = 0, *Wpos = 0, *Wsf = 0,
                *bsf = 0, *wbond = 0, *wdmg = 0, *bdmg = 0, *Wcproj = 0;

    bool mA = (n_in == 11);
    for (int i = 0; i < 11 && i < n_in; i++) if (in_sizes[i] != sigA[i]) mA = false;

    if (mA) {
        x      = (const float*)d_in[0];  Wdisp  = (const float*)d_in[1];
        Wval   = (const float*)d_in[2];  rpe    = (const float*)d_in[3];
        Wpos   = (const float*)d_in[4];  Wsf    = (const float*)d_in[5];
        bsf    = (const float*)d_in[6];  wbond  = (const float*)d_in[7];
        wdmg   = (const float*)d_in[8];  bdmg   = (const float*)d_in[9];
        Wcproj = (const float*)d_in[10];
    } else {
        int seen1M = 0, seen512 = 0, seen16 = 0;
        for (int i = 0; i < n_in; i++) {
            const float* p = (const float*)d_in[i];
            switch (in_sizes[i]) {
                case 8388608: x = p; break;
                case 262144:  Wdisp = p; break;
                case 256:     Wpos = p; break;
                case 32:      bsf = p; break;
                case 1:       bdmg = p; break;
                case 1048576: if (seen1M++ == 0) Wval = p; else Wcproj = p; break;
                case 512:     if (seen512++ == 0) rpe = p; else Wsf = p; break;
                case 16:      if (seen16++ == 0) wbond = p; else wdmg = p; break;
                default: break;
            }
        }
    }
    float* out = (float*)d_out;

    float *p_disp, *p_val, *p_attn, *p_posf;
    cudaGetSymbolAddress((void**)&p_disp, g_disp);
    cudaGetSymbolAddress((void**)&p_val,  g_val);
    cudaGetSymbolAddress((void**)&p_attn, g_attn);
    cudaGetSymbolAddress((void**)&p_posf, g_posf);

    const int M = BATCH * T_LEN;   // 8192

    posfeat_kernel<<<1, 512>>>(rpe, Wpos, p_posf);

    // disp = x @ W_disp  (8192 x 256, K=1024)
    {
        dim3 grid((NH * BD) / 128, M / 128);
        sgemm128<<<grid, 256>>>(x, Wdisp, p_disp, M, NH * BD, C_DIM);
    }
    // val = x @ W_val    (8192 x 1024, K=1024)
    {
        dim3 grid(C_DIM / 128, M / 128);
        sgemm128<<<grid, 256>>>(x, Wval, p_val, M, C_DIM, C_DIM);
    }
    // windowed attention -> (B,T,C)
    {
        const int total = BATCH * NH * T_LEN;   // 131072
        attn_naive<<<(total + 255) / 256, 256>>>(p_disp, p_val, Wsf, bsf,
                                                 wbond, wdmg, bdmg, p_posf, p_attn);
    }
    // out = attn @ W_cproj (8192 x 1024, K=1024)
    {
        dim3 grid(C_DIM / 128, M / 128);
        sgemm128<<<grid, 256>>>(p_attn, Wcproj, out, M, C_DIM, C_DIM);
    }
}

// round 7
// speedup vs baseline: 1.6138x; 1.1901x over previous
#include <cuda_runtime.h>
#include <cuda_bf16.h>
#include <math_constants.h>
#include <mma.h>

using namespace nvcuda;

// Problem constants
#define BATCH 2
#define T_LEN 4096
#define C_DIM 1024
#define NH 16
#define HS 64
#define BD 16
#define DELTA 32

// ---------------------------------------------------------------------------
// Scratch (no allocations allowed)
// ---------------------------------------------------------------------------
__device__ float g_disp[BATCH * T_LEN * (NH * BD)];   // (B,T,256)
__device__ float g_val [BATCH * T_LEN * C_DIM];       // (B,T,1024)
__device__ float g_attn[BATCH * T_LEN * C_DIM];       // (B,T,1024)
__device__ float g_posf[DELTA * BD];                  // (32,16)

// bf16 hi/lo split buffers
__device__ __nv_bfloat16 g_xh[BATCH * T_LEN * C_DIM], g_xl[BATCH * T_LEN * C_DIM];
__device__ __nv_bfloat16 g_ah[BATCH * T_LEN * C_DIM], g_al[BATCH * T_LEN * C_DIM];
__device__ __nv_bfloat16 g_wdh[C_DIM * NH * BD], g_wdl[C_DIM * NH * BD];
__device__ __nv_bfloat16 g_wvh[C_DIM * C_DIM], g_wvl[C_DIM * C_DIM];
__device__ __nv_bfloat16 g_wch[C_DIM * C_DIM], g_wcl[C_DIM * C_DIM];

// ---------------------------------------------------------------------------
// f32 -> (bf16 hi, bf16 lo) split:  v ≈ hi + lo, |lo| <= 2^-9 |v|
// ---------------------------------------------------------------------------
__global__ void split_bf16(const float* __restrict__ in,
                           __nv_bfloat16* __restrict__ hi,
                           __nv_bfloat16* __restrict__ lo, int n)
{
    int i = blockIdx.x * blockDim.x + threadIdx.x;
    if (i >= n) return;
    float v = in[i];
    __nv_bfloat16 h = __float2bfloat16(v);
    float r = v - __bfloat162float(h);
    hi[i] = h;
    lo[i] = __float2bfloat16(r);
}

// ---------------------------------------------------------------------------
// pos_feat = rel_pos_emb (32,16) @ W_pos (16,16)
// ---------------------------------------------------------------------------
__global__ void posfeat_kernel(const float* __restrict__ rpe,
                               const float* __restrict__ Wpos,
                               float* __restrict__ out)
{
    int i = threadIdx.x;
    if (i >= DELTA * BD) return;
    int d = i / BD, k = i % BD;
    float a = 0.f;
    for (int q = 0; q < BD; q++) a += rpe[d * BD + q] * Wpos[q * BD + k];
    out[i] = a;
}

// ---------------------------------------------------------------------------
// Tensor-core split-bf16 GEMM: C[M,N] = A[M,K] @ B[K,N] (fp32 accurate)
// Block 128x128, K-tile 16, 256 threads (8 warps), warp tile 32x64.
// C += Ahi*Bhi + Ahi*Blo + Alo*Bhi  (Alo*Blo dropped, ~2^-18 rel err)
// Requires M%128==0, N%128==0, K%16==0.
// ---------------------------------------------------------------------------
#define BM 128
#define BN 128
#define BK 16

__global__ void __launch_bounds__(256) wgemm_split(
    const __nv_bfloat16* __restrict__ Ahi, const __nv_bfloat16* __restrict__ Alo,
    const __nv_bfloat16* __restrict__ Bhi, const __nv_bfloat16* __restrict__ Blo,
    float* __restrict__ C, int M, int N, int K)
{
    __shared__ __nv_bfloat16 sAhi[BM][BK];
    __shared__ __nv_bfloat16 sAlo[BM][BK];
    __shared__ __nv_bfloat16 sBhi[BK][BN];
    __shared__ __nv_bfloat16 sBlo[BK][BN];

    const int tid  = threadIdx.x;
    const int warp = tid / 32;
    const int wm   = warp / 2;     // 0..3  -> 32-row strip
    const int wn   = warp % 2;     // 0..1  -> 64-col strip
    const int bm   = blockIdx.y * BM;
    const int bn   = blockIdx.x * BN;

    wmma::fragment<wmma::accumulator, 16, 16, 16, float> acc[2][4];
    for (int i = 0; i < 2; i++)
        for (int j = 0; j < 4; j++)
            wmma::fill_fragment(acc[i][j], 0.f);

    for (int k0 = 0; k0 < K; k0 += BK) {
        // A tile: 128x16, 2048 elems, 8 per thread
        for (int l = tid; l < BM * BK; l += 256) {
            int r = l / BK, c = l % BK;
            size_t gi = (size_t)(bm + r) * K + (k0 + c);
            sAhi[r][c] = Ahi[gi];
            sAlo[r][c] = Alo[gi];
        }
        // B tile: 16x128, coalesced over columns
        for (int l = tid; l < BK * BN; l += 256) {
            int r = l / BN, c = l % BN;
            size_t gi = (size_t)(k0 + r) * N + (bn + c);
            sBhi[r][c] = Bhi[gi];
            sBlo[r][c] = Blo[gi];
        }
        __syncthreads();

        wmma::fragment<wmma::matrix_a, 16, 16, 16, __nv_bfloat16, wmma::row_major> ah[2], al[2];
        wmma::fragment<wmma::matrix_b, 16, 16, 16, __nv_bfloat16, wmma::row_major> bh[4], bl[4];

        for (int i = 0; i < 2; i++) {
            wmma::load_matrix_sync(ah[i], &sAhi[wm * 32 + i * 16][0], BK);
            wmma::load_matrix_sync(al[i], &sAlo[wm * 32 + i * 16][0], BK);
        }
        for (int j = 0; j < 4; j++) {
            wmma::load_matrix_sync(bh[j], &sBhi[0][wn * 64 + j * 16], BN);
            wmma::load_matrix_sync(bl[j], &sBlo[0][wn * 64 + j * 16], BN);
        }

        for (int i = 0; i < 2; i++)
            for (int j = 0; j < 4; j++) {
                wmma::mma_sync(acc[i][j], ah[i], bh[j], acc[i][j]);
                wmma::mma_sync(acc[i][j], ah[i], bl[j], acc[i][j]);
                wmma::mma_sync(acc[i][j], al[i], bh[j], acc[i][j]);
            }
        __syncthreads();
    }

    for (int i = 0; i < 2; i++)
        for (int j = 0; j < 4; j++)
            wmma::store_matrix_sync(
                &C[(size_t)(bm + wm * 32 + i * 16) * N + (bn + wn * 64 + j * 16)],
                acc[i][j], N, wmma::mem_row_major);
}

// ---------------------------------------------------------------------------
// Literal windowed attention: one thread per (b, n, t).
// (UNCHANGED from the passing round-5/6 version.)
// ---------------------------------------------------------------------------
__device__ __forceinline__ float gelu_ref(float x) {
    return 0.5f * x * (1.f + erff(x * 0.7071067811865476f));
}

__global__ void attn_naive(
    const float* __restrict__ disp,   // (B,T,256), channel = n*BD + i
    const float* __restrict__ val,    // (B,T,1024), channel = n*HS + h
    const float* __restrict__ Wsf,    // (16,32) row-major
    const float* __restrict__ bsf,    // (32)
    const float* __restrict__ wbond,  // (16)
    const float* __restrict__ wdmg,   // (16)
    const float* __restrict__ bdmg,   // scalar
    const float* __restrict__ posf,   // (32,16) row-major [d][k]
    float* __restrict__ attn)         // (B,T,1024), channel = n*HS + h
{
    const int g = blockIdx.x * blockDim.x + threadIdx.x;   // (b*NH+n)*T + t
    if (g >= BATCH * NH * T_LEN) return;
    const int t  = g % T_LEN;
    const int bn = g / T_LEN;
    const int b  = bn / NH, n = bn % NH;

    float center[BD];
    for (int i = 0; i < BD; i++)
        center[i] = disp[((size_t)b * T_LEN + t) * 256 + n * BD + i];

    const float bdm = bdmg[0];

    float score[DELTA];
    for (int d = 0; d < DELTA; d++) {
        const int j = t + d - (DELTA - 1);
        float strain[BD];
        if (j >= 0) {
            for (int i = 0; i < BD; i++)
                strain[i] = disp[((size_t)b * T_LEN + j) * 256 + n * BD + i] - center[i];
        } else {
            for (int i = 0; i < BD; i++) strain[i] = -center[i];
        }

        float bond = 0.f;
        for (int k = 0; k < BD; k++) {
            float f = bsf[k];
            for (int i = 0; i < BD; i++) f += strain[i] * Wsf[i * 32 + k];
            f += posf[d * BD + k];
            bond += gelu_ref(f) * wbond[k];
        }
        float dz = 0.f;
        for (int k = 0; k < BD; k++) {
            float f = bsf[BD + k];
            for (int i = 0; i < BD; i++) f += strain[i] * Wsf[i * 32 + BD + k];
            dz += gelu_ref(f) * wdmg[k];
        }
        const float damage = 1.f / (1.f + expf(-(dz + bdm)));

        score[d] = (j >= 0) ? (bond - 10.f * damage) : -CUDART_INF_F;
    }

    float m = -CUDART_INF_F;
    for (int d = 0; d < DELTA; d++) m = fmaxf(m, score[d]);
    float ssum = 0.f;
    for (int d = 0; d < DELTA; d++) { score[d] = expf(score[d] - m); ssum += score[d]; }
    const float inv = 1.f / ssum;
    for (int d = 0; d < DELTA; d++) score[d] *= inv;

    float* orow = attn + ((size_t)b * T_LEN + t) * C_DIM + n * HS;
    for (int h = 0; h < HS; h++) {
        float acc = 0.f;
        for (int d = 0; d < DELTA; d++) {
            const int j = t + d - (DELTA - 1);
            if (j >= 0)
                acc += score[d] * val[((size_t)b * T_LEN + j) * C_DIM + n * HS + h];
        }
        orow[h] = acc;
    }
}

// ---------------------------------------------------------------------------
// Launch
// ---------------------------------------------------------------------------
extern "C" void kernel_launch(void* const* d_in, const int* in_sizes, int n_in,
                              void* d_out, int out_size)
{
    static const int sigA[11] = {8388608, 262144, 1048576, 512, 256, 512, 32, 16, 16, 1, 1048576};

    const float *x = 0, *Wdisp = 0, *Wval = 0, *rpe = 0, *Wpos = 0, *Wsf = 0,
                *bsf = 0, *wbond = 0, *wdmg = 0, *bdmg = 0, *Wcproj = 0;

    bool mA = (n_in == 11);
    for (int i = 0; i < 11 && i < n_in; i++) if (in_sizes[i] != sigA[i]) mA = false;

    if (mA) {
        x      = (const float*)d_in[0];  Wdisp  = (const float*)d_in[1];
        Wval   = (const float*)d_in[2];  rpe    = (const float*)d_in[3];
        Wpos   = (const float*)d_in[4];  Wsf    = (const float*)d_in[5];
        bsf    = (const float*)d_in[6];  wbond  = (const float*)d_in[7];
        wdmg   = (const float*)d_in[8];  bdmg   = (const float*)d_in[9];
        Wcproj = (const float*)d_in[10];
    } else {
        int seen1M = 0, seen512 = 0, seen16 = 0;
        for (int i = 0; i < n_in; i++) {
            const float* p = (const float*)d_in[i];
            switch (in_sizes[i]) {
                case 8388608: x = p; break;
                case 262144:  Wdisp = p; break;
                case 256:     Wpos = p; break;
                case 32:      bsf = p; break;
                case 1:       bdmg = p; break;
                case 1048576: if (seen1M++ == 0) Wval = p; else Wcproj = p; break;
                case 512:     if (seen512++ == 0) rpe = p; else Wsf = p; break;
                case 16:      if (seen16++ == 0) wbond = p; else wdmg = p; break;
                default: break;
            }
        }
    }
    float* out = (float*)d_out;

    float *p_disp, *p_val, *p_attn, *p_posf;
    cudaGetSymbolAddress((void**)&p_disp, g_disp);
    cudaGetSymbolAddress((void**)&p_val,  g_val);
    cudaGetSymbolAddress((void**)&p_attn, g_attn);
    cudaGetSymbolAddress((void**)&p_posf, g_posf);

    __nv_bfloat16 *xh, *xl, *ah, *al, *wdh, *wdl, *wvh, *wvl, *wch, *wcl;
    cudaGetSymbolAddress((void**)&xh,  g_xh);   cudaGetSymbolAddress((void**)&xl,  g_xl);
    cudaGetSymbolAddress((void**)&ah,  g_ah);   cudaGetSymbolAddress((void**)&al,  g_al);
    cudaGetSymbolAddress((void**)&wdh, g_wdh);  cudaGetSymbolAddress((void**)&wdl, g_wdl);
    cudaGetSymbolAddress((void**)&wvh, g_wvh);  cudaGetSymbolAddress((void**)&wvl, g_wvl);
    cudaGetSymbolAddress((void**)&wch, g_wch);  cudaGetSymbolAddress((void**)&wcl, g_wcl);

    const int M = BATCH * T_LEN;   // 8192
    const int NX = M * C_DIM;      // 8388608

    posfeat_kernel<<<1, 512>>>(rpe, Wpos, p_posf);

    // Split inputs/weights to bf16 hi/lo
    split_bf16<<<(NX + 255) / 256, 256>>>(x, xh, xl, NX);
    split_bf16<<<(C_DIM * NH * BD + 255) / 256, 256>>>(Wdisp, wdh, wdl, C_DIM * NH * BD);
    split_bf16<<<(C_DIM * C_DIM + 255) / 256, 256>>>(Wval, wvh, wvl, C_DIM * C_DIM);
    split_bf16<<<(C_DIM * C_DIM + 255) / 256, 256>>>(Wcproj, wch, wcl, C_DIM * C_DIM);

    // disp = x @ W_disp  (8192 x 256, K=1024)
    {
        dim3 grid((NH * BD) / BN, M / BM);
        wgemm_split<<<grid, 256>>>(xh, xl, wdh, wdl, p_disp, M, NH * BD, C_DIM);
    }
    // val = x @ W_val    (8192 x 1024, K=1024)
    {
        dim3 grid(C_DIM / BN, M / BM);
        wgemm_split<<<grid, 256>>>(xh, xl, wvh, wvl, p_val, M, C_DIM, C_DIM);
    }
    // windowed attention -> (B,T,C)
    {
        const int total = BATCH * NH * T_LEN;   // 131072
        attn_naive<<<(total + 255) / 256, 256>>>(p_disp, p_val, Wsf, bsf,
                                                 wbond, wdmg, bdmg, p_posf, p_attn);
    }
    // split attn, then out = attn @ W_cproj (8192 x 1024, K=1024)
    split_bf16<<<(NX + 255) / 256, 256>>>(p_attn, ah, al, NX);
    {
        dim3 grid(C_DIM / BN, M / BM);
        wgemm_split<<<grid, 256>>>(ah, al, wch, wcl, out, M, C_DIM, C_DIM);
    }
}

// round 8
// speedup vs baseline: 1.8452x; 1.1434x over previous
#include <cuda_runtime.h>
#include <cuda_bf16.h>
#include <math_constants.h>
#include <mma.h>

using namespace nvcuda;

// Problem constants
#define BATCH 2
#define T_LEN 4096
#define C_DIM 1024
#define NH 16
#define HS 64
#define BD 16
#define DELTA 32

// ---------------------------------------------------------------------------
// Scratch (no allocations allowed)
// ---------------------------------------------------------------------------
__device__ float g_disp[BATCH * T_LEN * (NH * BD)];   // (B,T,256)
__device__ float g_val [BATCH * T_LEN * C_DIM];       // (B,T,1024)
__device__ float g_attn[BATCH * T_LEN * C_DIM];       // (B,T,1024)
__device__ float g_posf[DELTA * BD];                  // (32,16)

// bf16 hi/lo split buffers
__device__ __nv_bfloat16 g_xh[BATCH * T_LEN * C_DIM], g_xl[BATCH * T_LEN * C_DIM];
__device__ __nv_bfloat16 g_ah[BATCH * T_LEN * C_DIM], g_al[BATCH * T_LEN * C_DIM];
__device__ __nv_bfloat16 g_wdh[C_DIM * NH * BD], g_wdl[C_DIM * NH * BD];
__device__ __nv_bfloat16 g_wvh[C_DIM * C_DIM], g_wvl[C_DIM * C_DIM];
__device__ __nv_bfloat16 g_wch[C_DIM * C_DIM], g_wcl[C_DIM * C_DIM];

// ---------------------------------------------------------------------------
// f32 -> (bf16 hi, bf16 lo) split:  v ≈ hi + lo
// ---------------------------------------------------------------------------
__global__ void split_bf16(const float* __restrict__ in,
                           __nv_bfloat16* __restrict__ hi,
                           __nv_bfloat16* __restrict__ lo, int n)
{
    int i = blockIdx.x * blockDim.x + threadIdx.x;
    if (i >= n) return;
    float v = in[i];
    __nv_bfloat16 h = __float2bfloat16(v);
    float r = v - __bfloat162float(h);
    hi[i] = h;
    lo[i] = __float2bfloat16(r);
}

// ---------------------------------------------------------------------------
// pos_feat = rel_pos_emb (32,16) @ W_pos (16,16)
// ---------------------------------------------------------------------------
__global__ void posfeat_kernel(const float* __restrict__ rpe,
                               const float* __restrict__ Wpos,
                               float* __restrict__ out)
{
    int i = threadIdx.x;
    if (i >= DELTA * BD) return;
    int d = i / BD, k = i % BD;
    float a = 0.f;
    for (int q = 0; q < BD; q++) a += rpe[d * BD + q] * Wpos[q * BD + k];
    out[i] = a;
}

// ---------------------------------------------------------------------------
// Tensor-core split-bf16 GEMM: C = A @ B with fp32-grade accuracy.
// Block 128x128, K-tile 32, 256 threads (8 warps), warp tile 32x64.
// smem padded to 136 elems/row (272B stride) -> conflict-free ldmatrix.
// A stored transposed in smem, loaded as col_major fragments.
// C += Ahi*Bhi + Ahi*Blo + Alo*Bhi   (Alo*Blo dropped, ~2^-18)
// ---------------------------------------------------------------------------
#define BM 128
#define BN 128
#define BK 32
#define LDP 136   // padded leading dim

__global__ void __launch_bounds__(256) wgemm_split(
    const __nv_bfloat16* __restrict__ Ahi, const __nv_bfloat16* __restrict__ Alo,
    const __nv_bfloat16* __restrict__ Bhi, const __nv_bfloat16* __restrict__ Blo,
    float* __restrict__ C, int M, int N, int K)
{
    __shared__ __nv_bfloat16 sAhi[BK][LDP];   // A^T : sA[k][m]
    __shared__ __nv_bfloat16 sAlo[BK][LDP];
    __shared__ __nv_bfloat16 sBhi[BK][LDP];   // B   : sB[k][n]
    __shared__ __nv_bfloat16 sBlo[BK][LDP];

    const int tid  = threadIdx.x;
    const int warp = tid / 32;
    const int wm   = warp / 2;     // 0..3 -> 32-row strip
    const int wn   = warp % 2;     // 0..1 -> 64-col strip
    const int bm   = blockIdx.y * BM;
    const int bn   = blockIdx.x * BN;

    wmma::fragment<wmma::accumulator, 16, 16, 16, float> acc[2][4];
    for (int i = 0; i < 2; i++)
        for (int j = 0; j < 4; j++)
            wmma::fill_fragment(acc[i][j], 0.f);

    for (int k0 = 0; k0 < K; k0 += BK) {
        // A tile: 128 rows x 32 k. Read coalesced over k, store transposed.
        // l = r*32 + c ; r = row in tile, c = k offset.
        for (int l = tid; l < BM * BK; l += 256) {
            int r = l / BK, c = l % BK;
            size_t gi = (size_t)(bm + r) * K + (k0 + c);
            sAhi[c][r] = Ahi[gi];
            sAlo[c][r] = Alo[gi];
        }
        // B tile: 32 k x 128 n. Coalesced over n, stored direct.
        for (int l = tid; l < BK * BN; l += 256) {
            int r = l / BN, c = l % BN;
            size_t gi = (size_t)(k0 + r) * N + (bn + c);
            sBhi[r][c] = Bhi[gi];
            sBlo[r][c] = Blo[gi];
        }
        __syncthreads();

        for (int kk = 0; kk < BK; kk += 16) {
            wmma::fragment<wmma::matrix_a, 16, 16, 16, __nv_bfloat16, wmma::col_major> ah[2], al[2];
            wmma::fragment<wmma::matrix_b, 16, 16, 16, __nv_bfloat16, wmma::row_major> bh[4], bl[4];

            for (int i = 0; i < 2; i++) {
                // col_major: A(m,k) at base[m + k*LDP]; tile origin (m=wm*32+i*16, k=kk)
                wmma::load_matrix_sync(ah[i], &sAhi[kk][wm * 32 + i * 16], LDP);
                wmma::load_matrix_sync(al[i], &sAlo[kk][wm * 32 + i * 16], LDP);
            }
            for (int j = 0; j < 4; j++) {
                wmma::load_matrix_sync(bh[j], &sBhi[kk][wn * 64 + j * 16], LDP);
                wmma::load_matrix_sync(bl[j], &sBlo[kk][wn * 64 + j * 16], LDP);
            }

            for (int i = 0; i < 2; i++)
                for (int j = 0; j < 4; j++) {
                    wmma::mma_sync(acc[i][j], ah[i], bh[j], acc[i][j]);
                    wmma::mma_sync(acc[i][j], ah[i], bl[j], acc[i][j]);
                    wmma::mma_sync(acc[i][j], al[i], bh[j], acc[i][j]);
                }
        }
        __syncthreads();
    }

    for (int i = 0; i < 2; i++)
        for (int j = 0; j < 4; j++)
            wmma::store_matrix_sync(
                &C[(size_t)(bm + wm * 32 + i * 16) * N + (bn + wn * 64 + j * 16)],
                acc[i][j], N, wmma::mem_row_major);
}

// ---------------------------------------------------------------------------
// Literal windowed attention: one thread per (b, n, t).  (UNCHANGED)
// ---------------------------------------------------------------------------
__device__ __forceinline__ float gelu_ref(float x) {
    return 0.5f * x * (1.f + erff(x * 0.7071067811865476f));
}

__global__ void attn_naive(
    const float* __restrict__ disp,   // (B,T,256), channel = n*BD + i
    const float* __restrict__ val,    // (B,T,1024), channel = n*HS + h
    const float* __restrict__ Wsf,    // (16,32) row-major
    const float* __restrict__ bsf,    // (32)
    const float* __restrict__ wbond,  // (16)
    const float* __restrict__ wdmg,   // (16)
    const float* __restrict__ bdmg,   // scalar
    const float* __restrict__ posf,   // (32,16) row-major [d][k]
    float* __restrict__ attn)         // (B,T,1024), channel = n*HS + h
{
    const int g = blockIdx.x * blockDim.x + threadIdx.x;   // (b*NH+n)*T + t
    if (g >= BATCH * NH * T_LEN) return;
    const int t  = g % T_LEN;
    const int bn = g / T_LEN;
    const int b  = bn / NH, n = bn % NH;

    float center[BD];
    for (int i = 0; i < BD; i++)
        center[i] = disp[((size_t)b * T_LEN + t) * 256 + n * BD + i];

    const float bdm = bdmg[0];

    float score[DELTA];
    for (int d = 0; d < DELTA; d++) {
        const int j = t + d - (DELTA - 1);
        float strain[BD];
        if (j >= 0) {
            for (int i = 0; i < BD; i++)
                strain[i] = disp[((size_t)b * T_LEN + j) * 256 + n * BD + i] - center[i];
        } else {
            for (int i = 0; i < BD; i++) strain[i] = -center[i];
        }

        float bond = 0.f;
        for (int k = 0; k < BD; k++) {
            float f = bsf[k];
            for (int i = 0; i < BD; i++) f += strain[i] * Wsf[i * 32 + k];
            f += posf[d * BD + k];
            bond += gelu_ref(f) * wbond[k];
        }
        float dz = 0.f;
        for (int k = 0; k < BD; k++) {
            float f = bsf[BD + k];
            for (int i = 0; i < BD; i++) f += strain[i] * Wsf[i * 32 + BD + k];
            dz += gelu_ref(f) * wdmg[k];
        }
        const float damage = 1.f / (1.f + expf(-(dz + bdm)));

        score[d] = (j >= 0) ? (bond - 10.f * damage) : -CUDART_INF_F;
    }

    float m = -CUDART_INF_F;
    for (int d = 0; d < DELTA; d++) m = fmaxf(m, score[d]);
    float ssum = 0.f;
    for (int d = 0; d < DELTA; d++) { score[d] = expf(score[d] - m); ssum += score[d]; }
    const float inv = 1.f / ssum;
    for (int d = 0; d < DELTA; d++) score[d] *= inv;

    float* orow = attn + ((size_t)b * T_LEN + t) * C_DIM + n * HS;
    for (int h = 0; h < HS; h++) {
        float acc = 0.f;
        for (int d = 0; d < DELTA; d++) {
            const int j = t + d - (DELTA - 1);
            if (j >= 0)
                acc += score[d] * val[((size_t)b * T_LEN + j) * C_DIM + n * HS + h];
        }
        orow[h] = acc;
    }
}

// ---------------------------------------------------------------------------
// Launch
// ---------------------------------------------------------------------------
extern "C" void kernel_launch(void* const* d_in, const int* in_sizes, int n_in,
                              void* d_out, int out_size)
{
    static const int sigA[11] = {8388608, 262144, 1048576, 512, 256, 512, 32, 16, 16, 1, 1048576};

    const float *x = 0, *Wdisp = 0, *Wval = 0, *rpe = 0, *Wpos = 0, *Wsf = 0,
                *bsf = 0, *wbond = 0, *wdmg = 0, *bdmg = 0, *Wcproj = 0;

    bool mA = (n_in == 11);
    for (int i = 0; i < 11 && i < n_in; i++) if (in_sizes[i] != sigA[i]) mA = false;

    if (mA) {
        x      = (const float*)d_in[0];  Wdisp  = (const float*)d_in[1];
        Wval   = (const float*)d_in[2];  rpe    = (const float*)d_in[3];
        Wpos   = (const float*)d_in[4];  Wsf    = (const float*)d_in[5];
        bsf    = (const float*)d_in[6];  wbond  = (const float*)d_in[7];
        wdmg   = (const float*)d_in[8];  bdmg   = (const float*)d_in[9];
        Wcproj = (const float*)d_in[10];
    } else {
        int seen1M = 0, seen512 = 0, seen16 = 0;
        for (int i = 0; i < n_in; i++) {
            const float* p = (const float*)d_in[i];
            switch (in_sizes[i]) {
                case 8388608: x = p; break;
                case 262144:  Wdisp = p; break;
                case 256:     Wpos = p; break;
                case 32:      bsf = p; break;
                case 1:       bdmg = p; break;
                case 1048576: if (seen1M++ == 0) Wval = p; else Wcproj = p; break;
                case 512:     if (seen512++ == 0) rpe = p; else Wsf = p; break;
                case 16:      if (seen16++ == 0) wbond = p; else wdmg = p; break;
                default: break;
            }
        }
    }
    float* out = (float*)d_out;

    float *p_disp, *p_val, *p_attn, *p_posf;
    cudaGetSymbolAddress((void**)&p_disp, g_disp);
    cudaGetSymbolAddress((void**)&p_val,  g_val);
    cudaGetSymbolAddress((void**)&p_attn, g_attn);
    cudaGetSymbolAddress((void**)&p_posf, g_posf);

    __nv_bfloat16 *xh, *xl, *ah, *al, *wdh, *wdl, *wvh, *wvl, *wch, *wcl;
    cudaGetSymbolAddress((void**)&xh,  g_xh);   cudaGetSymbolAddress((void**)&xl,  g_xl);
    cudaGetSymbolAddress((void**)&ah,  g_ah);   cudaGetSymbolAddress((void**)&al,  g_al);
    cudaGetSymbolAddress((void**)&wdh, g_wdh);  cudaGetSymbolAddress((void**)&wdl, g_wdl);
    cudaGetSymbolAddress((void**)&wvh, g_wvh);  cudaGetSymbolAddress((void**)&wvl, g_wvl);
    cudaGetSymbolAddress((void**)&wch, g_wch);  cudaGetSymbolAddress((void**)&wcl, g_wcl);

    const int M = BATCH * T_LEN;   // 8192
    const int NX = M * C_DIM;      // 8388608

    posfeat_kernel<<<1, 512>>>(rpe, Wpos, p_posf);

    // Split inputs/weights to bf16 hi/lo
    split_bf16<<<(NX + 255) / 256, 256>>>(x, xh, xl, NX);
    split_bf16<<<(C_DIM * NH * BD + 255) / 256, 256>>>(Wdisp, wdh, wdl, C_DIM * NH * BD);
    split_bf16<<<(C_DIM * C_DIM + 255) / 256, 256>>>(Wval, wvh, wvl, C_DIM * C_DIM);
    split_bf16<<<(C_DIM * C_DIM + 255) / 256, 256>>>(Wcproj, wch, wcl, C_DIM * C_DIM);

    // disp = x @ W_disp  (8192 x 256, K=1024)
    {
        dim3 grid((NH * BD) / BN, M / BM);
        wgemm_split<<<grid, 256>>>(xh, xl, wdh, wdl, p_disp, M, NH * BD, C_DIM);
    }
    // val = x @ W_val    (8192 x 1024, K=1024)
    {
        dim3 grid(C_DIM / BN, M / BM);
        wgemm_split<<<grid, 256>>>(xh, xl, wvh, wvl, p_val, M, C_DIM, C_DIM);
    }
    // windowed attention -> (B,T,C)
    {
        const int total = BATCH * NH * T_LEN;   // 131072
        attn_naive<<<(total + 255) / 256, 256>>>(p_disp, p_val, Wsf, bsf,
                                                 wbond, wdmg, bdmg, p_posf, p_attn);
    }
    // split attn, then out = attn @ W_cproj (8192 x 1024, K=1024)
    split_bf16<<<(NX + 255) / 256, 256>>>(p_attn, ah, al, NX);
    {
        dim3 grid(C_DIM / BN, M / BM);
        wgemm_split<<<grid, 256>>>(ah, al, wch, wcl, out, M, C_DIM, C_DIM);
    }
}

// round 10
// speedup vs baseline: 2.3520x; 1.2746x over previous
#include <cuda_runtime.h>
#include <cuda_bf16.h>
#include <math_constants.h>
#include <mma.h>

using namespace nvcuda;

// Problem constants
#define BATCH 2
#define T_LEN 4096
#define C_DIM 1024
#define NH 16
#define HS 64
#define BD 16
#define DELTA 32

// ---------------------------------------------------------------------------
// Scratch (no allocations allowed)
// ---------------------------------------------------------------------------
__device__ float g_disp[BATCH * T_LEN * (NH * BD)];   // (B,T,256)
__device__ float g_val [BATCH * T_LEN * C_DIM];       // (B,T,1024)
__device__ float g_attn[BATCH * T_LEN * C_DIM];       // (B,T,1024)
__device__ float g_posf[DELTA * BD];                  // (32,16)

// bf16 hi/lo split buffers (aligned for 16B vector access)
__device__ __align__(16) __nv_bfloat16 g_xh[BATCH * T_LEN * C_DIM], g_xl[BATCH * T_LEN * C_DIM];
__device__ __align__(16) __nv_bfloat16 g_ah[BATCH * T_LEN * C_DIM], g_al[BATCH * T_LEN * C_DIM];
__device__ __align__(16) __nv_bfloat16 g_wdh[C_DIM * NH * BD], g_wdl[C_DIM * NH * BD];
__device__ __align__(16) __nv_bfloat16 g_wvh[C_DIM * C_DIM], g_wvl[C_DIM * C_DIM];
__device__ __align__(16) __nv_bfloat16 g_wch[C_DIM * C_DIM], g_wcl[C_DIM * C_DIM];

// ---------------------------------------------------------------------------
// Scalar f32 -> (bf16 hi, bf16 lo) split  (UNCHANGED from passing R8)
// ---------------------------------------------------------------------------
__global__ void split_bf16(const float* __restrict__ in,
                           __nv_bfloat16* __restrict__ hi,
                           __nv_bfloat16* __restrict__ lo, int n)
{
    int i = blockIdx.x * blockDim.x + threadIdx.x;
    if (i >= n) return;
    float v = in[i];
    __nv_bfloat16 h = __float2bfloat16(v);
    float r = v - __bfloat162float(h);
    hi[i] = h;
    lo[i] = __float2bfloat16(r);
}

// ---------------------------------------------------------------------------
// pos_feat = rel_pos_emb (32,16) @ W_pos (16,16)
// ---------------------------------------------------------------------------
__global__ void posfeat_kernel(const float* __restrict__ rpe,
                               const float* __restrict__ Wpos,
                               float* __restrict__ out)
{
    int i = threadIdx.x;
    if (i >= DELTA * BD) return;
    int d = i / BD, k = i % BD;
    float a = 0.f;
    for (int q = 0; q < BD; q++) a += rpe[d * BD + q] * Wpos[q * BD + k];
    out[i] = a;
}

// ---------------------------------------------------------------------------
// Tensor-core split-bf16 GEMM with VECTORIZED loaders (the one change).
// Block 128x128, K-tile 32, 256 threads (8 warps), warp tile 32x64.
// A row-major in smem [128][40] (80B = 20-word stride, conflict-free ldmatrix).
// B row-major in smem [32][136] (272B = 68-word stride, conflict-free).
// C += Ahi*Bhi + Ahi*Blo + Alo*Bhi  (Alo*Blo dropped)
// ---------------------------------------------------------------------------
#define BM 128
#define BN 128
#define BK 32
#define LDA 40
#define LDB 136

__global__ void __launch_bounds__(256) wgemm_split(
    const __nv_bfloat16* __restrict__ Ahi, const __nv_bfloat16* __restrict__ Alo,
    const __nv_bfloat16* __restrict__ Bhi, const __nv_bfloat16* __restrict__ Blo,
    float* __restrict__ C, int M, int N, int K)
{
    __shared__ __align__(16) __nv_bfloat16 sAhi[BM][LDA];
    __shared__ __align__(16) __nv_bfloat16 sAlo[BM][LDA];
    __shared__ __align__(16) __nv_bfloat16 sBhi[BK][LDB];
    __shared__ __align__(16) __nv_bfloat16 sBlo[BK][LDB];

    const int tid  = threadIdx.x;
    const int warp = tid / 32;
    const int wm   = warp / 2;     // 0..3 -> 32-row strip
    const int wn   = warp % 2;     // 0..1 -> 64-col strip
    const int bm   = blockIdx.y * BM;
    const int bn   = blockIdx.x * BN;

    wmma::fragment<wmma::accumulator, 16, 16, 16, float> acc[2][4];
    for (int i = 0; i < 2; i++)
        for (int j = 0; j < 4; j++)
            wmma::fill_fragment(acc[i][j], 0.f);

    for (int k0 = 0; k0 < K; k0 += BK) {
        // A tile: 128 rows x 32 k = 512 uint4 (8 bf16 each); 2 per thread.
        // l = r*4 + c4 ; smem offset r*LDA + c4*8 (80B stride, 16B chunks).
        for (int l = tid; l < 512; l += 256) {
            int r  = l / 4;          // row 0..127
            int c4 = l % 4;          // 16B chunk in row (4 x 8 = 32 k-elems)
            size_t gi = (size_t)(bm + r) * K + k0 + c4 * 8;
            *reinterpret_cast<uint4*>(&sAhi[r][c4 * 8]) =
                *reinterpret_cast<const uint4*>(&Ahi[gi]);
            *reinterpret_cast<uint4*>(&sAlo[r][c4 * 8]) =
                *reinterpret_cast<const uint4*>(&Alo[gi]);
        }
        // B tile: 32 k-rows x 128 n = 512 uint4; coalesced over n.
        for (int l = tid; l < 512; l += 256) {
            int r   = l / 16;        // k row 0..31
            int c16 = l % 16;        // 16 chunks x 8 = 128 cols
            size_t gi = (size_t)(k0 + r) * N + bn + c16 * 8;
            *reinterpret_cast<uint4*>(&sBhi[r][c16 * 8]) =
                *reinterpret_cast<const uint4*>(&Bhi[gi]);
            *reinterpret_cast<uint4*>(&sBlo[r][c16 * 8]) =
                *reinterpret_cast<const uint4*>(&Blo[gi]);
        }
        __syncthreads();

        for (int kk = 0; kk < BK; kk += 16) {
            wmma::fragment<wmma::matrix_a, 16, 16, 16, __nv_bfloat16, wmma::row_major> ah[2], al[2];
            wmma::fragment<wmma::matrix_b, 16, 16, 16, __nv_bfloat16, wmma::row_major> bh[4], bl[4];

            for (int i = 0; i < 2; i++) {
                wmma::load_matrix_sync(ah[i], &sAhi[wm * 32 + i * 16][kk], LDA);
                wmma::load_matrix_sync(al[i], &sAlo[wm * 32 + i * 16][kk], LDA);
            }
            for (int j = 0; j < 4; j++) {
                wmma::load_matrix_sync(bh[j], &sBhi[kk][wn * 64 + j * 16], LDB);
                wmma::load_matrix_sync(bl[j], &sBlo[kk][wn * 64 + j * 16], LDB);
            }

            for (int i = 0; i < 2; i++)
                for (int j = 0; j < 4; j++) {
                    wmma::mma_sync(acc[i][j], ah[i], bh[j], acc[i][j]);
                    wmma::mma_sync(acc[i][j], ah[i], bl[j], acc[i][j]);
                    wmma::mma_sync(acc[i][j], al[i], bh[j], acc[i][j]);
                }
        }
        __syncthreads();
    }

    for (int i = 0; i < 2; i++)
        for (int j = 0; j < 4; j++)
            wmma::store_matrix_sync(
                &C[(size_t)(bm + wm * 32 + i * 16) * N + (bn + wn * 64 + j * 16)],
                acc[i][j], N, wmma::mem_row_major);
}

// ---------------------------------------------------------------------------
// Literal windowed attention: one thread per (b, n, t).
// (BYTE-IDENTICAL to the passing R5-R8 version.)
// ---------------------------------------------------------------------------
__device__ __forceinline__ float gelu_ref(float x) {
    return 0.5f * x * (1.f + erff(x * 0.7071067811865476f));
}

__global__ void attn_naive(
    const float* __restrict__ disp,   // (B,T,256), channel = n*BD + i
    const float* __restrict__ val,    // (B,T,1024), channel = n*HS + h
    const float* __restrict__ Wsf,    // (16,32) row-major
    const float* __restrict__ bsf,    // (32)
    const float* __restrict__ wbond,  // (16)
    const float* __restrict__ wdmg,   // (16)
    const float* __restrict__ bdmg,   // scalar
    const float* __restrict__ posf,   // (32,16) row-major [d][k]
    float* __restrict__ attn)         // (B,T,1024), channel = n*HS + h
{
    const int g = blockIdx.x * blockDim.x + threadIdx.x;   // (b*NH+n)*T + t
    if (g >= BATCH * NH * T_LEN) return;
    const int t  = g % T_LEN;
    const int bn = g / T_LEN;
    const int b  = bn / NH, n = bn % NH;

    float center[BD];
    for (int i = 0; i < BD; i++)
        center[i] = disp[((size_t)b * T_LEN + t) * 256 + n * BD + i];

    const float bdm = bdmg[0];

    float score[DELTA];
    for (int d = 0; d < DELTA; d++) {
        const int j = t + d - (DELTA - 1);
        float strain[BD];
        if (j >= 0) {
            for (int i = 0; i < BD; i++)
                strain[i] = disp[((size_t)b * T_LEN + j) * 256 + n * BD + i] - center[i];
        } else {
            for (int i = 0; i < BD; i++) strain[i] = -center[i];
        }

        float bond = 0.f;
        for (int k = 0; k < BD; k++) {
            float f = bsf[k];
            for (int i = 0; i < BD; i++) f += strain[i] * Wsf[i * 32 + k];
            f += posf[d * BD + k];
            bond += gelu_ref(f) * wbond[k];
        }
        float dz = 0.f;
        for (int k = 0; k < BD; k++) {
            float f = bsf[BD + k];
            for (int i = 0; i < BD; i++) f += strain[i] * Wsf[i * 32 + BD + k];
            dz += gelu_ref(f) * wdmg[k];
        }
        const float damage = 1.f / (1.f + expf(-(dz + bdm)));

        score[d] = (j >= 0) ? (bond - 10.f * damage) : -CUDART_INF_F;
    }

    float m = -CUDART_INF_F;
    for (int d = 0; d < DELTA; d++) m = fmaxf(m, score[d]);
    float ssum = 0.f;
    for (int d = 0; d < DELTA; d++) { score[d] = expf(score[d] - m); ssum += score[d]; }
    const float inv = 1.f / ssum;
    for (int d = 0; d < DELTA; d++) score[d] *= inv;

    float* orow = attn + ((size_t)b * T_LEN + t) * C_DIM + n * HS;
    for (int h = 0; h < HS; h++) {
        float acc = 0.f;
        for (int d = 0; d < DELTA; d++) {
            const int j = t + d - (DELTA - 1);
            if (j >= 0)
                acc += score[d] * val[((size_t)b * T_LEN + j) * C_DIM + n * HS + h];
        }
        orow[h] = acc;
    }
}

// ---------------------------------------------------------------------------
// Launch
// ---------------------------------------------------------------------------
extern "C" void kernel_launch(void* const* d_in, const int* in_sizes, int n_in,
                              void* d_out, int out_size)
{
    static const int sigA[11] = {8388608, 262144, 1048576, 512, 256, 512, 32, 16, 16, 1, 1048576};

    const float *x = 0, *Wdisp = 0, *Wval = 0, *rpe = 0, *Wpos = 0, *Wsf = 0,
                *bsf = 0, *wbond = 0, *wdmg = 0, *bdmg = 0, *Wcproj = 0;

    bool mA = (n_in == 11);
    for (int i = 0; i < 11 && i < n_in; i++) if (in_sizes[i] != sigA[i]) mA = false;

    if (mA) {
        x      = (const float*)d_in[0];  Wdisp  = (const float*)d_in[1];
        Wval   = (const float*)d_in[2];  rpe    = (const float*)d_in[3];
        Wpos   = (const float*)d_in[4];  Wsf    = (const float*)d_in[5];
        bsf    = (const float*)d_in[6];  wbond  = (const float*)d_in[7];
        wdmg   = (const float*)d_in[8];  bdmg   = (const float*)d_in[9];
        Wcproj = (const float*)d_in[10];
    } else {
        int seen1M = 0, seen512 = 0, seen16 = 0;
        for (int i = 0; i < n_in; i++) {
            const float* p = (const float*)d_in[i];
            switch (in_sizes[i]) {
                case 8388608: x = p; break;
                case 262144:  Wdisp = p; break;
                case 256:     Wpos = p; break;
                case 32:      bsf = p; break;
                case 1:       bdmg = p; break;
                case 1048576: if (seen1M++ == 0) Wval = p; else Wcproj = p; break;
                case 512:     if (seen512++ == 0) rpe = p; else Wsf = p; break;
                case 16:      if (seen16++ == 0) wbond = p; else wdmg = p; break;
                default: break;
            }
        }
    }
    float* out = (float*)d_out;

    float *p_disp, *p_val, *p_attn, *p_posf;
    cudaGetSymbolAddress((void**)&p_disp, g_disp);
    cudaGetSymbolAddress((void**)&p_val,  g_val);
    cudaGetSymbolAddress((void**)&p_attn, g_attn);
    cudaGetSymbolAddress((void**)&p_posf, g_posf);

    __nv_bfloat16 *xh, *xl, *ah, *al, *wdh, *wdl, *wvh, *wvl, *wch, *wcl;
    cudaGetSymbolAddress((void**)&xh,  g_xh);   cudaGetSymbolAddress((void**)&xl,  g_xl);
    cudaGetSymbolAddress((void**)&ah,  g_ah);   cudaGetSymbolAddress((void**)&al,  g_al);
    cudaGetSymbolAddress((void**)&wdh, g_wdh);  cudaGetSymbolAddress((void**)&wdl, g_wdl);
    cudaGetSymbolAddress((void**)&wvh, g_wvh);  cudaGetSymbolAddress((void**)&wvl, g_wvl);
    cudaGetSymbolAddress((void**)&wch, g_wch);  cudaGetSymbolAddress((void**)&wcl, g_wcl);

    const int M = BATCH * T_LEN;   // 8192
    const int NX = M * C_DIM;      // 8388608

    posfeat_kernel<<<1, 512>>>(rpe, Wpos, p_posf);

    // Split inputs/weights to bf16 hi/lo (scalar, as in passing R8)
    split_bf16<<<(NX + 255) / 256, 256>>>(x, xh, xl, NX);
    split_bf16<<<(C_DIM * NH * BD + 255) / 256, 256>>>(Wdisp, wdh, wdl, C_DIM * NH * BD);
    split_bf16<<<(C_DIM * C_DIM + 255) / 256, 256>>>(Wval, wvh, wvl, C_DIM * C_DIM);
    split_bf16<<<(C_DIM * C_DIM + 255) / 256, 256>>>(Wcproj, wch, wcl, C_DIM * C_DIM);

    // disp = x @ W_disp  (8192 x 256, K=1024)
    {
        dim3 grid((NH * BD) / BN, M / BM);
        wgemm_split<<<grid, 256>>>(xh, xl, wdh, wdl, p_disp, M, NH * BD, C_DIM);
    }
    // val = x @ W_val    (8192 x 1024, K=1024)
    {
        dim3 grid(C_DIM / BN, M / BM);
        wgemm_split<<<grid, 256>>>(xh, xl, wvh, wvl, p_val, M, C_DIM, C_DIM);
    }
    // windowed attention -> (B,T,C)
    {
        const int total = BATCH * NH * T_LEN;   // 131072
        attn_naive<<<(total + 255) / 256, 256>>>(p_disp, p_val, Wsf, bsf,
                                                 wbond, wdmg, bdmg, p_posf, p_attn);
    }
    // split attn, then out = attn @ W_cproj (8192 x 1024, K=1024)
    split_bf16<<<(NX + 255) / 256, 256>>>(p_attn, ah, al, NX);
    {
        dim3 grid(C_DIM / BN, M / BM);
        wgemm_split<<<grid, 256>>>(ah, al, wch, wcl, out, M, C_DIM, C_DIM);
    }
}

// round 12
// speedup vs baseline: 2.4241x; 1.0307x over previous
#include <cuda_runtime.h>
#include <cuda_bf16.h>
#include <math_constants.h>
#include <mma.h>
#include <cstdint>

using namespace nvcuda;

// Problem constants
#define BATCH 2
#define T_LEN 4096
#define C_DIM 1024
#define NH 16
#define HS 64
#define BD 16
#define DELTA 32

// ---------------------------------------------------------------------------
// Scratch (no allocations allowed)
// ---------------------------------------------------------------------------
__device__ float g_disp[BATCH * T_LEN * (NH * BD)];   // (B,T,256)
__device__ float g_val [BATCH * T_LEN * C_DIM];       // (B,T,1024)
__device__ float g_attn[BATCH * T_LEN * C_DIM];       // (B,T,1024)
__device__ float g_posf[DELTA * BD];                  // (32,16)

// bf16 hi/lo split buffers (aligned for 16B vector access)
__device__ __align__(16) __nv_bfloat16 g_xh[BATCH * T_LEN * C_DIM], g_xl[BATCH * T_LEN * C_DIM];
__device__ __align__(16) __nv_bfloat16 g_ah[BATCH * T_LEN * C_DIM], g_al[BATCH * T_LEN * C_DIM];
__device__ __align__(16) __nv_bfloat16 g_wdh[C_DIM * NH * BD], g_wdl[C_DIM * NH * BD];
__device__ __align__(16) __nv_bfloat16 g_wvh[C_DIM * C_DIM], g_wvl[C_DIM * C_DIM];
__device__ __align__(16) __nv_bfloat16 g_wch[C_DIM * C_DIM], g_wcl[C_DIM * C_DIM];

// ---------------------------------------------------------------------------
// Scalar f32 -> (bf16 hi, bf16 lo) split  (UNCHANGED, trusted)
// ---------------------------------------------------------------------------
__global__ void split_bf16(const float* __restrict__ in,
                           __nv_bfloat16* __restrict__ hi,
                           __nv_bfloat16* __restrict__ lo, int n)
{
    int i = blockIdx.x * blockDim.x + threadIdx.x;
    if (i >= n) return;
    float v = in[i];
    __nv_bfloat16 h = __float2bfloat16(v);
    float r = v - __bfloat162float(h);
    hi[i] = h;
    lo[i] = __float2bfloat16(r);
}

// ---------------------------------------------------------------------------
// pos_feat = rel_pos_emb (32,16) @ W_pos (16,16)
// ---------------------------------------------------------------------------
__global__ void posfeat_kernel(const float* __restrict__ rpe,
                               const float* __restrict__ Wpos,
                               float* __restrict__ out)
{
    int i = threadIdx.x;
    if (i >= DELTA * BD) return;
    int d = i / BD, k = i % BD;
    float a = 0.f;
    for (int q = 0; q < BD; q++) a += rpe[d * BD + q] * Wpos[q * BD + k];
    out[i] = a;
}

// ---------------------------------------------------------------------------
// Double-buffered cp.async split-bf16 tensor-core GEMM.
// Block 128x128, K-tile 32, 256 threads (8 warps), warp tile 32x64.
// Per-stage smem layout (bytes, all 16B aligned):
//   Ahi [128][40] @ 0      (10240)
//   Alo [128][40] @ 10240  (10240)
//   Bhi [32][136] @ 20480  ( 8704)
//   Blo [32][136] @ 29184  ( 8704)
//   stage stride 37888, 2 stages = 75776 dynamic smem.
// C += Ahi*Bhi + Ahi*Blo + Alo*Bhi  (Alo*Blo dropped)
// ---------------------------------------------------------------------------
#define BM 128
#define BN 128
#define BK 32
#define LDA 40
#define LDB 136
#define STAGE_BYTES 37888
#define OFF_ALO 10240
#define OFF_BHI 20480
#define OFF_BLO 29184

__device__ __forceinline__ void cp_async16(void* smem_ptr, const void* gmem_ptr)
{
    unsigned int s = (unsigned int)__cvta_generic_to_shared(smem_ptr);
    asm volatile("cp.async.cg.shared.global [%0], [%1], 16;" :: "r"(s), "l"(gmem_ptr));
}

__global__ void __launch_bounds__(256) wgemm_split_pipe(
    const __nv_bfloat16* __restrict__ Ahi, const __nv_bfloat16* __restrict__ Alo,
    const __nv_bfloat16* __restrict__ Bhi, const __nv_bfloat16* __restrict__ Blo,
    float* __restrict__ C, int M, int N, int K)
{
    extern __shared__ __align__(16) char dynsmem[];

    const int tid  = threadIdx.x;
    const int warp = tid / 32;
    const int wm   = warp / 2;     // 0..3 -> 32-row strip
    const int wn   = warp % 2;     // 0..1 -> 64-col strip
    const int bm   = blockIdx.y * BM;
    const int bn   = blockIdx.x * BN;

    wmma::fragment<wmma::accumulator, 16, 16, 16, float> acc[2][4];
    for (int i = 0; i < 2; i++)
        for (int j = 0; j < 4; j++)
            wmma::fill_fragment(acc[i][j], 0.f);

    // issue async loads of k-tile k0 into stage s
    auto prefetch = [&](int s, int k0) {
        char* st = dynsmem + s * STAGE_BYTES;
        __nv_bfloat16* pAhi = reinterpret_cast<__nv_bfloat16*>(st);
        __nv_bfloat16* pAlo = reinterpret_cast<__nv_bfloat16*>(st + OFF_ALO);
        __nv_bfloat16* pBhi = reinterpret_cast<__nv_bfloat16*>(st + OFF_BHI);
        __nv_bfloat16* pBlo = reinterpret_cast<__nv_bfloat16*>(st + OFF_BLO);
        // A tile: 128 rows x 32 k = 512 x 16B chunks
        for (int l = tid; l < 512; l += 256) {
            int r  = l >> 2;         // row 0..127
            int c4 = l & 3;          // 16B chunk (8 bf16) within row
            size_t gi = (size_t)(bm + r) * K + k0 + c4 * 8;
            cp_async16(&pAhi[r * LDA + c4 * 8], &Ahi[gi]);
            cp_async16(&pAlo[r * LDA + c4 * 8], &Alo[gi]);
        }
        // B tile: 32 k-rows x 128 n = 512 x 16B chunks
        for (int l = tid; l < 512; l += 256) {
            int r   = l >> 4;        // k row 0..31
            int c16 = l & 15;        // 16 chunks x 8 = 128 cols
            size_t gi = (size_t)(k0 + r) * N + bn + c16 * 8;
            cp_async16(&pBhi[r * LDB + c16 * 8], &Bhi[gi]);
            cp_async16(&pBlo[r * LDB + c16 * 8], &Blo[gi]);
        }
        asm volatile("cp.async.commit_group;");
    };

    const int nIter = K / BK;
    prefetch(0, 0);

    for (int it = 0; it < nIter; it++) {
        if (it + 1 < nIter) {
            prefetch((it + 1) & 1, (it + 1) * BK);
            asm volatile("cp.async.wait_group 1;");
        } else {
            asm volatile("cp.async.wait_group 0;");
        }
        __syncthreads();

        char* st = dynsmem + (it & 1) * STAGE_BYTES;
        __nv_bfloat16* pAhi = reinterpret_cast<__nv_bfloat16*>(st);
        __nv_bfloat16* pAlo = reinterpret_cast<__nv_bfloat16*>(st + OFF_ALO);
        __nv_bfloat16* pBhi = reinterpret_cast<__nv_bfloat16*>(st + OFF_BHI);
        __nv_bfloat16* pBlo = reinterpret_cast<__nv_bfloat16*>(st + OFF_BLO);

        for (int kk = 0; kk < BK; kk += 16) {
            wmma::fragment<wmma::matrix_a, 16, 16, 16, __nv_bfloat16, wmma::row_major> ah[2], al[2];
            wmma::fragment<wmma::matrix_b, 16, 16, 16, __nv_bfloat16, wmma::row_major> bh[4], bl[4];

            for (int i = 0; i < 2; i++) {
                wmma::load_matrix_sync(ah[i], &pAhi[(wm * 32 + i * 16) * LDA + kk], LDA);
                wmma::load_matrix_sync(al[i], &pAlo[(wm * 32 + i * 16) * LDA + kk], LDA);
            }
            for (int j = 0; j < 4; j++) {
                wmma::load_matrix_sync(bh[j], &pBhi[kk * LDB + wn * 64 + j * 16], LDB);
                wmma::load_matrix_sync(bl[j], &pBlo[kk * LDB + wn * 64 + j * 16], LDB);
            }

            for (int i = 0; i < 2; i++)
                for (int j = 0; j < 4; j++) {
                    wmma::mma_sync(acc[i][j], ah[i], bh[j], acc[i][j]);
                    wmma::mma_sync(acc[i][j], ah[i], bl[j], acc[i][j]);
                    wmma::mma_sync(acc[i][j], al[i], bh[j], acc[i][j]);
                }
        }
        __syncthreads();
    }

    for (int i = 0; i < 2; i++)
        for (int j = 0; j < 4; j++)
            wmma::store_matrix_sync(
                &C[(size_t)(bm + wm * 32 + i * 16) * N + (bn + wn * 64 + j * 16)],
                acc[i][j], N, wmma::mem_row_major);
}

// ---------------------------------------------------------------------------
// Literal windowed attention: one thread per (b, n, t).  (UNCHANGED, trusted)
// ---------------------------------------------------------------------------
__device__ __forceinline__ float gelu_ref(float x) {
    return 0.5f * x * (1.f + erff(x * 0.7071067811865476f));
}

__global__ void attn_naive(
    const float* __restrict__ disp,   // (B,T,256), channel = n*BD + i
    const float* __restrict__ val,    // (B,T,1024), channel = n*HS + h
    const float* __restrict__ Wsf,    // (16,32) row-major
    const float* __restrict__ bsf,    // (32)
    const float* __restrict__ wbond,  // (16)
    const float* __restrict__ wdmg,   // (16)
    const float* __restrict__ bdmg,   // scalar
    const float* __restrict__ posf,   // (32,16) row-major [d][k]
    float* __restrict__ attn)         // (B,T,1024), channel = n*HS + h
{
    const int g = blockIdx.x * blockDim.x + threadIdx.x;   // (b*NH+n)*T + t
    if (g >= BATCH * NH * T_LEN) return;
    const int t  = g % T_LEN;
    const int bn = g / T_LEN;
    const int b  = bn / NH, n = bn % NH;

    float center[BD];
    for (int i = 0; i < BD; i++)
        center[i] = disp[((size_t)b * T_LEN + t) * 256 + n * BD + i];

    const float bdm = bdmg[0];

    float score[DELTA];
    for (int d = 0; d < DELTA; d++) {
        const int j = t + d - (DELTA - 1);
        float strain[BD];
        if (j >= 0) {
            for (int i = 0; i < BD; i++)
                strain[i] = disp[((size_t)b * T_LEN + j) * 256 + n * BD + i] - center[i];
        } else {
            for (int i = 0; i < BD; i++) strain[i] = -center[i];
        }

        float bond = 0.f;
        for (int k = 0; k < BD; k++) {
            float f = bsf[k];
            for (int i = 0; i < BD; i++) f += strain[i] * Wsf[i * 32 + k];
            f += posf[d * BD + k];
            bond += gelu_ref(f) * wbond[k];
        }
        float dz = 0.f;
        for (int k = 0; k < BD; k++) {
            float f = bsf[BD + k];
            for (int i = 0; i < BD; i++) f += strain[i] * Wsf[i * 32 + BD + k];
            dz += gelu_ref(f) * wdmg[k];
        }
        const float damage = 1.f / (1.f + expf(-(dz + bdm)));

        score[d] = (j >= 0) ? (bond - 10.f * damage) : -CUDART_INF_F;
    }

    float m = -CUDART_INF_F;
    for (int d = 0; d < DELTA; d++) m = fmaxf(m, score[d]);
    float ssum = 0.f;
    for (int d = 0; d < DELTA; d++) { score[d] = expf(score[d] - m); ssum += score[d]; }
    const float inv = 1.f / ssum;
    for (int d = 0; d < DELTA; d++) score[d] *= inv;

    float* orow = attn + ((size_t)b * T_LEN + t) * C_DIM + n * HS;
    for (int h = 0; h < HS; h++) {
        float acc = 0.f;
        for (int d = 0; d < DELTA; d++) {
            const int j = t + d - (DELTA - 1);
            if (j >= 0)
                acc += score[d] * val[((size_t)b * T_LEN + j) * C_DIM + n * HS + h];
        }
        orow[h] = acc;
    }
}

// ---------------------------------------------------------------------------
// Launch
// ---------------------------------------------------------------------------
extern "C" void kernel_launch(void* const* d_in, const int* in_sizes, int n_in,
                              void* d_out, int out_size)
{
    static const int sigA[11] = {8388608, 262144, 1048576, 512, 256, 512, 32, 16, 16, 1, 1048576};

    const float *x = 0, *Wdisp = 0, *Wval = 0, *rpe = 0, *Wpos = 0, *Wsf = 0,
                *bsf = 0, *wbond = 0, *wdmg = 0, *bdmg = 0, *Wcproj = 0;

    bool mA = (n_in == 11);
    for (int i = 0; i < 11 && i < n_in; i++) if (in_sizes[i] != sigA[i]) mA = false;

    if (mA) {
        x      = (const float*)d_in[0];  Wdisp  = (const float*)d_in[1];
        Wval   = (const float*)d_in[2];  rpe    = (const float*)d_in[3];
        Wpos   = (const float*)d_in[4];  Wsf    = (const float*)d_in[5];
        bsf    = (const float*)d_in[6];  wbond  = (const float*)d_in[7];
        wdmg   = (const float*)d_in[8];  bdmg   = (const float*)d_in[9];
        Wcproj = (const float*)d_in[10];
    } else {
        int seen1M = 0, seen512 = 0, seen16 = 0;
        for (int i = 0; i < n_in; i++) {
            const float* p = (const float*)d_in[i];
            switch (in_sizes[i]) {
                case 8388608: x = p; break;
                case 262144:  Wdisp = p; break;
                case 256:     Wpos = p; break;
                case 32:      bsf = p; break;
                case 1:       bdmg = p; break;
                case 1048576: if (seen1M++ == 0) Wval = p; else Wcproj = p; break;
                case 512:     if (seen512++ == 0) rpe = p; else Wsf = p; break;
                case 16:      if (seen16++ == 0) wbond = p; else wdmg = p; break;
                default: break;
            }
        }
    }
    float* out = (float*)d_out;

    float *p_disp, *p_val, *p_attn, *p_posf;
    cudaGetSymbolAddress((void**)&p_disp, g_disp);
    cudaGetSymbolAddress((void**)&p_val,  g_val);
    cudaGetSymbolAddress((void**)&p_attn, g_attn);
    cudaGetSymbolAddress((void**)&p_posf, g_posf);

    __nv_bfloat16 *xh, *xl, *ah, *al, *wdh, *wdl, *wvh, *wvl, *wch, *wcl;
    cudaGetSymbolAddress((void**)&xh,  g_xh);   cudaGetSymbolAddress((void**)&xl,  g_xl);
    cudaGetSymbolAddress((void**)&ah,  g_ah);   cudaGetSymbolAddress((void**)&al,  g_al);
    cudaGetSymbolAddress((void**)&wdh, g_wdh);  cudaGetSymbolAddress((void**)&wdl, g_wdl);
    cudaGetSymbolAddress((void**)&wvh, g_wvh);  cudaGetSymbolAddress((void**)&wvl, g_wvl);
    cudaGetSymbolAddress((void**)&wch, g_wch);  cudaGetSymbolAddress((void**)&wcl, g_wcl);

    const int M = BATCH * T_LEN;   // 8192
    const int NX = M * C_DIM;      // 8388608
    const int SMEM = 2 * STAGE_BYTES;   // 75776

    static bool attr_set = false;
    if (!attr_set) {
        cudaFuncSetAttribute(wgemm_split_pipe,
                             cudaFuncAttributeMaxDynamicSharedMemorySize, SMEM);
        attr_set = true;
    }

    posfeat_kernel<<<1, 512>>>(rpe, Wpos, p_posf);

    // Split inputs/weights to bf16 hi/lo (scalar, trusted)
    split_bf16<<<(NX + 255) / 256, 256>>>(x, xh, xl, NX);
    split_bf16<<<(C_DIM * NH * BD + 255) / 256, 256>>>(Wdisp, wdh, wdl, C_DIM * NH * BD);
    split_bf16<<<(C_DIM * C_DIM + 255) / 256, 256>>>(Wval, wvh, wvl, C_DIM * C_DIM);
    split_bf16<<<(C_DIM * C_DIM + 255) / 256, 256>>>(Wcproj, wch, wcl, C_DIM * C_DIM);

    // disp = x @ W_disp  (8192 x 256, K=1024)
    {
        dim3 grid((NH * BD) / BN, M / BM);
        wgemm_split_pipe<<<grid, 256, SMEM>>>(xh, xl, wdh, wdl, p_disp, M, NH * BD, C_DIM);
    }
    // val = x @ W_val    (8192 x 1024, K=1024)
    {
        dim3 grid(C_DIM / BN, M / BM);
        wgemm_split_pipe<<<grid, 256, SMEM>>>(xh, xl, wvh, wvl, p_val, M, C_DIM, C_DIM);
    }
    // windowed attention -> (B,T,C)
    {
        const int total = BATCH * NH * T_LEN;   // 131072
        attn_naive<<<(total + 255) / 256, 256>>>(p_disp, p_val, Wsf, bsf,
                                                 wbond, wdmg, bdmg, p_posf, p_attn);
    }
    // split attn, then out = attn @ W_cproj (8192 x 1024, K=1024)
    split_bf16<<<(NX + 255) / 256, 256>>>(p_attn, ah, al, NX);
    {
        dim3 grid(C_DIM / BN, M / BM);
        wgemm_split_pipe<<<grid, 256, SMEM>>>(ah, al, wch, wcl, out, M, C_DIM, C_DIM);
    }
}

// round 14
// speedup vs baseline: 2.7894x; 1.1507x over previous
#include <cuda_runtime.h>
#include <cuda_bf16.h>
#include <cuda_fp16.h>
#include <math_constants.h>
#include <mma.h>
#include <cstdint>

using namespace nvcuda;

// Problem constants
#define BATCH 2
#define T_LEN 4096
#define C_DIM 1024
#define NH 16
#define HS 64
#define BD 16
#define DELTA 32

// ---------------------------------------------------------------------------
// Scratch (no allocations allowed)
// ---------------------------------------------------------------------------
__device__ float g_disp[BATCH * T_LEN * (NH * BD)];
__device__ float g_val [BATCH * T_LEN * C_DIM];
__device__ float g_attn[BATCH * T_LEN * C_DIM];
__device__ float g_posf[DELTA * BD];

// fp16 operand buffers (aligned for 16B vector access)
__device__ __align__(16) __half g_xh[BATCH * T_LEN * C_DIM];
__device__ __align__(16) __half g_ah[BATCH * T_LEN * C_DIM];
__device__ __align__(16) __half g_wdh[C_DIM * NH * BD];
__device__ __align__(16) __half g_wvh[C_DIM * C_DIM];
__device__ __align__(16) __half g_wch[C_DIM * C_DIM];

// ---------------------------------------------------------------------------
// f32 -> fp16 convert
// ---------------------------------------------------------------------------
__global__ void to_half(const float* __restrict__ in,
                        __half* __restrict__ out, int n)
{
    int i = blockIdx.x * blockDim.x + threadIdx.x;
    if (i >= n) return;
    out[i] = __float2half(in[i]);
}

// ---------------------------------------------------------------------------
// pos_feat = rel_pos_emb (32,16) @ W_pos (16,16)
// ---------------------------------------------------------------------------
__global__ void posfeat_kernel(const float* __restrict__ rpe,
                               const float* __restrict__ Wpos,
                               float* __restrict__ out)
{
    int i = threadIdx.x;
    if (i >= DELTA * BD) return;
    int d = i / BD, k = i % BD;
    float a = 0.f;
    for (int q = 0; q < BD; q++) a += rpe[d * BD + q] * Wpos[q * BD + k];
    out[i] = a;
}

// ---------------------------------------------------------------------------
// Double-buffered cp.async fp16 tensor-core GEMM: C[M,N] = A[M,K] @ B[K,N].
// Block 128x128, K-tile 32, 256 threads (8 warps), warp tile 32x64.
// Per-stage smem (16B aligned):
//   A [128][40] halfs @ 0      (10240 B)  80B row stride, conflict-free
//   B [32][136] halfs @ 10240  ( 8704 B)  272B row stride, conflict-free
//   stage stride 18944, 2 stages = 37888 dynamic smem.
// ---------------------------------------------------------------------------
#define BM 128
#define BN 128
#define BK 32
#define LDA 40
#define LDB 136
#define STAGE_BYTES 18944
#define OFF_B 10240

__device__ __forceinline__ void cp_async16(void* smem_ptr, const void* gmem_ptr)
{
    unsigned int s = (unsigned int)__cvta_generic_to_shared(smem_ptr);
    asm volatile("cp.async.cg.shared.global [%0], [%1], 16;" :: "r"(s), "l"(gmem_ptr));
}

__global__ void __launch_bounds__(256) hgemm_pipe(
    const __half* __restrict__ A, const __half* __restrict__ B,
    float* __restrict__ C, int M, int N, int K)
{
    extern __shared__ __align__(16) char dynsmem[];

    const int tid  = threadIdx.x;
    const int warp = tid / 32;
    const int wm   = warp / 2;     // 0..3 -> 32-row strip
    const int wn   = warp % 2;     // 0..1 -> 64-col strip
    const int bm   = blockIdx.y * BM;
    const int bn   = blockIdx.x * BN;

    wmma::fragment<wmma::accumulator, 16, 16, 16, float> acc[2][4];
    for (int i = 0; i < 2; i++)
        for (int j = 0; j < 4; j++)
            wmma::fill_fragment(acc[i][j], 0.f);

    auto prefetch = [&](int s, int k0) {
        char* st = dynsmem + s * STAGE_BYTES;
        __half* pA = reinterpret_cast<__half*>(st);
        __half* pB = reinterpret_cast<__half*>(st + OFF_B);
        // A tile: 128 rows x 32 k halfs = 512 x 16B chunks (8 halfs each)
        for (int l = tid; l < 512; l += 256) {
            int r  = l >> 2;          // row 0..127
            int c4 = l & 3;           // chunk within row (4 x 8 = 32 k)
            size_t gi = (size_t)(bm + r) * K + k0 + c4 * 8;
            cp_async16(&pA[r * LDA + c4 * 8], &A[gi]);
        }
        // B tile: 32 k-rows x 128 n halfs = 512 x 16B chunks
        for (int l = tid; l < 512; l += 256) {
            int r   = l >> 4;         // k row 0..31
            int c16 = l & 15;         // 16 chunks x 8 = 128 cols
            size_t gi = (size_t)(k0 + r) * N + bn + c16 * 8;
            cp_async16(&pB[r * LDB + c16 * 8], &B[gi]);
        }
        asm volatile("cp.async.commit_group;");
    };

    const int nIter = K / BK;
    prefetch(0, 0);

    for (int it = 0; it < nIter; it++) {
        if (it + 1 < nIter) {
            prefetch((it + 1) & 1, (it + 1) * BK);
            asm volatile("cp.async.wait_group 1;");
        } else {
            asm volatile("cp.async.wait_group 0;");
        }
        __syncthreads();

        char* st = dynsmem + (it & 1) * STAGE_BYTES;
        __half* pA = reinterpret_cast<__half*>(st);
        __half* pB = reinterpret_cast<__half*>(st + OFF_B);

        for (int kk = 0; kk < BK; kk += 16) {
            wmma::fragment<wmma::matrix_a, 16, 16, 16, __half, wmma::row_major> af[2];
            wmma::fragment<wmma::matrix_b, 16, 16, 16, __half, wmma::row_major> bf[4];

            for (int i = 0; i < 2; i++)
                wmma::load_matrix_sync(af[i], &pA[(wm * 32 + i * 16) * LDA + kk], LDA);
            for (int j = 0; j < 4; j++)
                wmma::load_matrix_sync(bf[j], &pB[kk * LDB + wn * 64 + j * 16], LDB);

            for (int i = 0; i < 2; i++)
                for (int j = 0; j < 4; j++)
                    wmma::mma_sync(acc[i][j], af[i], bf[j], acc[i][j]);
        }
        __syncthreads();
    }

    for (int i = 0; i < 2; i++)
        for (int j = 0; j < 4; j++)
            wmma::store_matrix_sync(
                &C[(size_t)(bm + wm * 32 + i * 16) * N + (bn + wn * 64 + j * 16)],
                acc[i][j], N, wmma::mem_row_major);
}

// ---------------------------------------------------------------------------
// Literal windowed attention: one thread per (b, n, t).  (UNCHANGED, trusted)
// ---------------------------------------------------------------------------
__device__ __forceinline__ float gelu_ref(float x) {
    return 0.5f * x * (1.f + erff(x * 0.7071067811865476f));
}

__global__ void attn_naive(
    const float* __restrict__ disp, const float* __restrict__ val,
    const float* __restrict__ Wsf, const float* __restrict__ bsf,
    const float* __restrict__ wbond, const float* __restrict__ wdmg,
    const float* __restrict__ bdmg, const float* __restrict__ posf,
    float* __restrict__ attn)
{
    const int g = blockIdx.x * blockDim.x + threadIdx.x;
    if (g >= BATCH * NH * T_LEN) return;
    const int t = g % T_LEN;
    const int bn = g / T_LEN;
    const int b = bn / NH, n = bn % NH;

    float center[BD];
    for (int i = 0; i < BD; i++)
        center[i] = disp[((size_t)b * T_LEN + t) * 256 + n * BD + i];

    const float bdm = bdmg[0];
    float score[DELTA];
    for (int d = 0; d < DELTA; d++) {
        const int j = t + d - (DELTA - 1);
        float strain[BD];
        if (j >= 0) {
            for (int i = 0; i < BD; i++)
                strain[i] = disp[((size_t)b * T_LEN + j) * 256 + n * BD + i] - center[i];
        } else {
            for (int i = 0; i < BD; i++) strain[i] = -center[i];
        }
        float bond = 0.f;
        for (int k = 0; k < BD; k++) {
            float f = bsf[k];
            for (int i = 0; i < BD; i++) f += strain[i] * Wsf[i * 32 + k];
            f += posf[d * BD + k];
            bond += gelu_ref(f) * wbond[k];
        }
        float dz = 0.f;
        for (int k = 0; k < BD; k++) {
            float f = bsf[BD + k];
            for (int i = 0; i < BD; i++) f += strain[i] * Wsf[i * 32 + BD + k];
            dz += gelu_ref(f) * wdmg[k];
        }
        const float damage = 1.f / (1.f + expf(-(dz + bdm)));
        score[d] = (j >= 0) ? (bond - 10.f * damage) : -CUDART_INF_F;
    }
    float m = -CUDART_INF_F;
    for (int d = 0; d < DELTA; d++) m = fmaxf(m, score[d]);
    float ssum = 0.f;
    for (int d = 0; d < DELTA; d++) { score[d] = expf(score[d] - m); ssum += score[d]; }
    const float inv = 1.f / ssum;
    for (int d = 0; d < DELTA; d++) score[d] *= inv;

    float* orow = attn + ((size_t)b * T_LEN + t) * C_DIM + n * HS;
    for (int h = 0; h < HS; h++) {
        float acc = 0.f;
        for (int d = 0; d < DELTA; d++) {
            const int j = t + d - (DELTA - 1);
            if (j >= 0)
                acc += score[d] * val[((size_t)b * T_LEN + j) * C_DIM + n * HS + h];
        }
        orow[h] = acc;
    }
}

// ---------------------------------------------------------------------------
// Launch
// ---------------------------------------------------------------------------
extern "C" void kernel_launch(void* const* d_in, const int* in_sizes, int n_in,
                              void* d_out, int out_size)
{
    static const int sigA[11] = {8388608, 262144, 1048576, 512, 256, 512, 32, 16, 16, 1, 1048576};

    const float *x = 0, *Wdisp = 0, *Wval = 0, *rpe = 0, *Wpos = 0, *Wsf = 0,
                *bsf = 0, *wbond = 0, *wdmg = 0, *bdmg = 0, *Wcproj = 0;

    bool mA = (n_in == 11);
    for (int i = 0; i < 11 && i < n_in; i++) if (in_sizes[i] != sigA[i]) mA = false;

    if (mA) {
        x      = (const float*)d_in[0];  Wdisp  = (const float*)d_in[1];
        Wval   = (const float*)d_in[2];  rpe    = (const float*)d_in[3];
        Wpos   = (const float*)d_in[4];  Wsf    = (const float*)d_in[5];
        bsf    = (const float*)d_in[6];  wbond  = (const float*)d_in[7];
        wdmg   = (const float*)d_in[8];  bdmg   = (const float*)d_in[9];
        Wcproj = (const float*)d_in[10];
    } else {
        int seen1M = 0, seen512 = 0, seen16 = 0;
        for (int i = 0; i < n_in; i++) {
            const float* p = (const float*)d_in[i];
            switch (in_sizes[i]) {
                case 8388608: x = p; break;
                case 262144:  Wdisp = p; break;
                case 256:     Wpos = p; break;
                case 32:      bsf = p; break;
                case 1:       bdmg = p; break;
                case 1048576: if (seen1M++ == 0) Wval = p; else Wcproj = p; break;
                case 512:     if (seen512++ == 0) rpe = p; else Wsf = p; break;
                case 16:      if (seen16++ == 0) wbond = p; else wdmg = p; break;
                default: break;
            }
        }
    }
    float* out = (float*)d_out;

    float *p_disp, *p_val, *p_attn, *p_posf;
    cudaGetSymbolAddress((void**)&p_disp, g_disp);
    cudaGetSymbolAddress((void**)&p_val,  g_val);
    cudaGetSymbolAddress((void**)&p_attn, g_attn);
    cudaGetSymbolAddress((void**)&p_posf, g_posf);

    __half *xh, *ah, *wdh, *wvh, *wch;
    cudaGetSymbolAddress((void**)&xh,  g_xh);
    cudaGetSymbolAddress((void**)&ah,  g_ah);
    cudaGetSymbolAddress((void**)&wdh, g_wdh);
    cudaGetSymbolAddress((void**)&wvh, g_wvh);
    cudaGetSymbolAddress((void**)&wch, g_wch);

    const int M = BATCH * T_LEN;   // 8192
    const int NX = M * C_DIM;      // 8388608
    const int SMEM = 2 * STAGE_BYTES;   // 37888

    static bool attr_set = false;
    if (!attr_set) {
        cudaFuncSetAttribute(hgemm_pipe,
                             cudaFuncAttributeMaxDynamicSharedMemorySize, SMEM);
        attr_set = true;
    }

    posfeat_kernel<<<1, 512>>>(rpe, Wpos, p_posf);

    // Convert operands to fp16
    to_half<<<(NX + 255) / 256, 256>>>(x, xh, NX);
    to_half<<<(C_DIM * NH * BD + 255) / 256, 256>>>(Wdisp, wdh, C_DIM * NH * BD);
    to_half<<<(C_DIM * C_DIM + 255) / 256, 256>>>(Wval, wvh, C_DIM * C_DIM);
    to_half<<<(C_DIM * C_DIM + 255) / 256, 256>>>(Wcproj, wch, C_DIM * C_DIM);

    // disp = x @ W_disp  (8192 x 256, K=1024)
    {
        dim3 grid((NH * BD) / BN, M / BM);
        hgemm_pipe<<<grid, 256, SMEM>>>(xh, wdh, p_disp, M, 256, C_DIM);
    }
    // val = x @ W_val    (8192 x 1024, K=1024)
    {
        dim3 grid(C_DIM / BN, M / BM);
        hgemm_pipe<<<grid, 256, SMEM>>>(xh, wvh, p_val, M, C_DIM, C_DIM);
    }
    // windowed attention -> (B,T,C)
    {
        const int total = BATCH * NH * T_LEN;   // 131072
        attn_naive<<<(total + 255) / 256, 256>>>(p_disp, p_val, Wsf, bsf,
                                                 wbond, wdmg, bdmg, p_posf, p_attn);
    }
    // convert attn, then out = attn @ W_cproj (8192 x 1024, K=1024)
    to_half<<<(NX + 255) / 256, 256>>>(p_attn, ah, NX);
    {
        dim3 grid(C_DIM / BN, M / BM);
        hgemm_pipe<<<grid, 256, SMEM>>>(ah, wch, out, M, C_DIM, C_DIM);
    }
}

// round 15
// speedup vs baseline: 3.1675x; 1.1355x over previous
#include <cuda_runtime.h>
#include <cuda_bf16.h>
#include <cuda_fp16.h>
#include <math_constants.h>
#include <mma.h>
#include <cstdint>

using namespace nvcuda;

// Problem constants
#define BATCH 2
#define T_LEN 4096
#define C_DIM 1024
#define NH 16
#define HS 64
#define BD 16
#define DELTA 32

// ---------------------------------------------------------------------------
// Scratch (no allocations allowed)
// ---------------------------------------------------------------------------
__device__ float g_disp[BATCH * T_LEN * (NH * BD)];
__device__ float g_val [BATCH * T_LEN * C_DIM];
__device__ float g_proj[BATCH * T_LEN * NH * 2 * BD];   // (B,T,NH,32) strain projections
__device__ float g_posf[DELTA * BD];

// fp16 operand buffers (aligned for 16B vector access)
__device__ __align__(16) __half g_xh[BATCH * T_LEN * C_DIM];
__device__ __align__(16) __half g_ah[BATCH * T_LEN * C_DIM];
__device__ __align__(16) __half g_wdh[C_DIM * NH * BD];
__device__ __align__(16) __half g_wvh[C_DIM * C_DIM];
__device__ __align__(16) __half g_wch[C_DIM * C_DIM];

// ---------------------------------------------------------------------------
// f32 -> fp16 convert
// ---------------------------------------------------------------------------
__global__ void to_half(const float* __restrict__ in,
                        __half* __restrict__ out, int n)
{
    int i = blockIdx.x * blockDim.x + threadIdx.x;
    if (i >= n) return;
    out[i] = __float2half(in[i]);
}

// ---------------------------------------------------------------------------
// pos_feat = rel_pos_emb (32,16) @ W_pos (16,16)
// ---------------------------------------------------------------------------
__global__ void posfeat_kernel(const float* __restrict__ rpe,
                               const float* __restrict__ Wpos,
                               float* __restrict__ out)
{
    int i = threadIdx.x;
    if (i >= DELTA * BD) return;
    int d = i / BD, k = i % BD;
    float a = 0.f;
    for (int q = 0; q < BD; q++) a += rpe[d * BD + q] * Wpos[q * BD + k];
    out[i] = a;
}

// ---------------------------------------------------------------------------
// proj[r][k] = sum_i disp_row[r][i] * Wsf[i][k]    (r = (b*T+t)*NH + n)
// disp rows of 16 floats ARE contiguous in (b,t,n) order; proj rows of 32.
// ---------------------------------------------------------------------------
__global__ void proj_kernel(const float* __restrict__ disp,
                            const float* __restrict__ Wsf,
                            float* __restrict__ proj)
{
    __shared__ float sW[BD * 2 * BD];   // 16 x 32
    const int tid = threadIdx.x;
    for (int i = tid; i < BD * 2 * BD; i += 256) sW[i] = Wsf[i];
    __syncthreads();

    const int g = blockIdx.x * 256 + tid;           // row over B*T*NH = 131072
    if (g >= BATCH * T_LEN * NH) return;

    float xr[BD];
    const float* dr = disp + (size_t)g * BD;
#pragma unroll
    for (int i = 0; i < BD; i += 4) {
        float4 v = *reinterpret_cast<const float4*>(dr + i);
        xr[i] = v.x; xr[i + 1] = v.y; xr[i + 2] = v.z; xr[i + 3] = v.w;
    }

    float* pr = proj + (size_t)g * (2 * BD);
#pragma unroll
    for (int k4 = 0; k4 < 2 * BD; k4 += 4) {
        float4 o;
        float a0 = 0.f, a1 = 0.f, a2 = 0.f, a3 = 0.f;
#pragma unroll
        for (int i = 0; i < BD; i++) {
            const float xi = xr[i];
            a0 = fmaf(xi, sW[i * 32 + k4 + 0], a0);
            a1 = fmaf(xi, sW[i * 32 + k4 + 1], a1);
            a2 = fmaf(xi, sW[i * 32 + k4 + 2], a2);
            a3 = fmaf(xi, sW[i * 32 + k4 + 3], a3);
        }
        o.x = a0; o.y = a1; o.z = a2; o.w = a3;
        *reinterpret_cast<float4*>(pr + k4) = o;
    }
}

// ---------------------------------------------------------------------------
// Double-buffered cp.async fp16 tensor-core GEMM  (BYTE-IDENTICAL to R14)
// ---------------------------------------------------------------------------
#define BM 128
#define BN 128
#define BK 32
#define LDA 40
#define LDB 136
#define STAGE_BYTES 18944
#define OFF_B 10240

__device__ __forceinline__ void cp_async16(void* smem_ptr, const void* gmem_ptr)
{
    unsigned int s = (unsigned int)__cvta_generic_to_shared(smem_ptr);
    asm volatile("cp.async.cg.shared.global [%0], [%1], 16;" :: "r"(s), "l"(gmem_ptr));
}

__global__ void __launch_bounds__(256) hgemm_pipe(
    const __half* __restrict__ A, const __half* __restrict__ B,
    float* __restrict__ C, int M, int N, int K)
{
    extern __shared__ __align__(16) char dynsmem[];

    const int tid  = threadIdx.x;
    const int warp = tid / 32;
    const int wm   = warp / 2;
    const int wn   = warp % 2;
    const int bm   = blockIdx.y * BM;
    const int bn   = blockIdx.x * BN;

    wmma::fragment<wmma::accumulator, 16, 16, 16, float> acc[2][4];
    for (int i = 0; i < 2; i++)
        for (int j = 0; j < 4; j++)
            wmma::fill_fragment(acc[i][j], 0.f);

    auto prefetch = [&](int s, int k0) {
        char* st = dynsmem + s * STAGE_BYTES;
        __half* pA = reinterpret_cast<__half*>(st);
        __half* pB = reinterpret_cast<__half*>(st + OFF_B);
        for (int l = tid; l < 512; l += 256) {
            int r  = l >> 2;
            int c4 = l & 3;
            size_t gi = (size_t)(bm + r) * K + k0 + c4 * 8;
            cp_async16(&pA[r * LDA + c4 * 8], &A[gi]);
        }
        for (int l = tid; l < 512; l += 256) {
            int r   = l >> 4;
            int c16 = l & 15;
            size_t gi = (size_t)(k0 + r) * N + bn + c16 * 8;
            cp_async16(&pB[r * LDB + c16 * 8], &B[gi]);
        }
        asm volatile("cp.async.commit_group;");
    };

    const int nIter = K / BK;
    prefetch(0, 0);

    for (int it = 0; it < nIter; it++) {
        if (it + 1 < nIter) {
            prefetch((it + 1) & 1, (it + 1) * BK);
            asm volatile("cp.async.wait_group 1;");
        } else {
            asm volatile("cp.async.wait_group 0;");
        }
        __syncthreads();

        char* st = dynsmem + (it & 1) * STAGE_BYTES;
        __half* pA = reinterpret_cast<__half*>(st);
        __half* pB = reinterpret_cast<__half*>(st + OFF_B);

        for (int kk = 0; kk < BK; kk += 16) {
            wmma::fragment<wmma::matrix_a, 16, 16, 16, __half, wmma::row_major> af[2];
            wmma::fragment<wmma::matrix_b, 16, 16, 16, __half, wmma::row_major> bf[4];

            for (int i = 0; i < 2; i++)
                wmma::load_matrix_sync(af[i], &pA[(wm * 32 + i * 16) * LDA + kk], LDA);
            for (int j = 0; j < 4; j++)
                wmma::load_matrix_sync(bf[j], &pB[kk * LDB + wn * 64 + j * 16], LDB);

            for (int i = 0; i < 2; i++)
                for (int j = 0; j < 4; j++)
                    wmma::mma_sync(acc[i][j], af[i], bf[j], acc[i][j]);
        }
        __syncthreads();
    }

    for (int i = 0; i < 2; i++)
        for (int j = 0; j < 4; j++)
            wmma::store_matrix_sync(
                &C[(size_t)(bm + wm * 32 + i * 16) * N + (bn + wn * 64 + j * 16)],
                acc[i][j], N, wmma::mem_row_major);
}

// ---------------------------------------------------------------------------
// Windowed attention using precomputed projections.
// Same thread-per-site structure and math as the trusted naive kernel;
// strain@Wsf replaced by proj[j] - proj[t].  Output written directly as fp16.
// ---------------------------------------------------------------------------
__device__ __forceinline__ float gelu_ref(float x) {
    return 0.5f * x * (1.f + erff(x * 0.7071067811865476f));
}

__global__ void __launch_bounds__(256) attn_proj(
    const float* __restrict__ proj,   // (B,T,NH,32)
    const float* __restrict__ val,    // (B,T,1024)
    const float* __restrict__ bsf,    // (32)
    const float* __restrict__ wbond,  // (16)
    const float* __restrict__ wdmg,   // (16)
    const float* __restrict__ bdmg,   // scalar
    const float* __restrict__ posf,   // (32,16)
    __half* __restrict__ attn_h)      // (B,T,1024) fp16
{
    __shared__ float cpos[DELTA][BD];   // bsf[k] + posf[d][k]
    __shared__ float cdmg[BD];          // bsf[16+k]
    __shared__ float swb[BD], swd[BD];

    const int tid = threadIdx.x;
    for (int i = tid; i < DELTA * BD; i += 256)
        cpos[i / BD][i % BD] = bsf[i % BD] + posf[i];
    if (tid < BD) {
        cdmg[tid] = bsf[BD + tid];
        swb[tid] = wbond[tid];
        swd[tid] = wdmg[tid];
    }
    __syncthreads();

    const int g = blockIdx.x * blockDim.x + tid;      // (b*NH+n)*T + t
    if (g >= BATCH * NH * T_LEN) return;
    const int t  = g % T_LEN;
    const int bn = g / T_LEN;
    const int b  = bn / NH, n = bn % NH;
    const float bdm = bdmg[0];

    // center projection row
    float pt[2 * BD];
    const float* ptp = proj + (((size_t)b * T_LEN + t) * NH + n) * (2 * BD);
#pragma unroll
    for (int i = 0; i < 2 * BD; i += 4) {
        float4 v = *reinterpret_cast<const float4*>(ptp + i);
        pt[i] = v.x; pt[i + 1] = v.y; pt[i + 2] = v.z; pt[i + 3] = v.w;
    }

    float score[DELTA];
    for (int d = 0; d < DELTA; d++) {
        const int j = t + d - (DELTA - 1);
        if (j < 0) { score[d] = -CUDART_INF_F; continue; }
        const float* pjp = proj + (((size_t)b * T_LEN + j) * NH + n) * (2 * BD);
        float bond = 0.f, dz = 0.f;
#pragma unroll
        for (int k = 0; k < BD; k++) {
            float fb = pjp[k] - pt[k] + cpos[d][k];
            bond = fmaf(gelu_ref(fb), swb[k], bond);
            float fd = pjp[BD + k] - pt[BD + k] + cdmg[k];
            dz = fmaf(gelu_ref(fd), swd[k], dz);
        }
        const float damage = 1.f / (1.f + expf(-(dz + bdm)));
        score[d] = bond - 10.f * damage;
    }

    float m = -CUDART_INF_F;
    for (int d = 0; d < DELTA; d++) m = fmaxf(m, score[d]);
    float ssum = 0.f;
    for (int d = 0; d < DELTA; d++) { score[d] = expf(score[d] - m); ssum += score[d]; }
    const float inv = 1.f / ssum;
    for (int d = 0; d < DELTA; d++) score[d] *= inv;

    __half* orow = attn_h + ((size_t)b * T_LEN + t) * C_DIM + n * HS;
    for (int h = 0; h < HS; h++) {
        float acc = 0.f;
        for (int d = 0; d < DELTA; d++) {
            const int j = t + d - (DELTA - 1);
            if (j >= 0)
                acc += score[d] * val[((size_t)b * T_LEN + j) * C_DIM + n * HS + h];
        }
        orow[h] = __float2half(acc);
    }
}

// ---------------------------------------------------------------------------
// Launch
// ---------------------------------------------------------------------------
extern "C" void kernel_launch(void* const* d_in, const int* in_sizes, int n_in,
                              void* d_out, int out_size)
{
    static const int sigA[11] = {8388608, 262144, 1048576, 512, 256, 512, 32, 16, 16, 1, 1048576};

    const float *x = 0, *Wdisp = 0, *Wval = 0, *rpe = 0, *Wpos = 0, *Wsf = 0,
                *bsf = 0, *wbond = 0, *wdmg = 0, *bdmg = 0, *Wcproj = 0;

    bool mA = (n_in == 11);
    for (int i = 0; i < 11 && i < n_in; i++) if (in_sizes[i] != sigA[i]) mA = false;

    if (mA) {
        x      = (const float*)d_in[0];  Wdisp  = (const float*)d_in[1];
        Wval   = (const float*)d_in[2];  rpe    = (const float*)d_in[3];
        Wpos   = (const float*)d_in[4];  Wsf    = (const float*)d_in[5];
        bsf    = (const float*)d_in[6];  wbond  = (const float*)d_in[7];
        wdmg   = (const float*)d_in[8];  bdmg   = (const float*)d_in[9];
        Wcproj = (const float*)d_in[10];
    } else {
        int seen1M = 0, seen512 = 0, seen16 = 0;
        for (int i = 0; i < n_in; i++) {
            const float* p = (const float*)d_in[i];
            switch (in_sizes[i]) {
                case 8388608: x = p; break;
                case 262144:  Wdisp = p; break;
                case 256:     Wpos = p; break;
                case 32:      bsf = p; break;
                case 1:       bdmg = p; break;
                case 1048576: if (seen1M++ == 0) Wval = p; else Wcproj = p; break;
                case 512:     if (seen512++ == 0) rpe = p; else Wsf = p; break;
                case 16:      if (seen16++ == 0) wbond = p; else wdmg = p; break;
                default: break;
            }
        }
    }
    float* out = (float*)d_out;

    float *p_disp, *p_val, *p_proj, *p_posf;
    cudaGetSymbolAddress((void**)&p_disp, g_disp);
    cudaGetSymbolAddress((void**)&p_val,  g_val);
    cudaGetSymbolAddress((void**)&p_proj, g_proj);
    cudaGetSymbolAddress((void**)&p_posf, g_posf);

    __half *xh, *ah, *wdh, *wvh, *wch;
    cudaGetSymbolAddress((void**)&xh,  g_xh);
    cudaGetSymbolAddress((void**)&ah,  g_ah);
    cudaGetSymbolAddress((void**)&wdh, g_wdh);
    cudaGetSymbolAddress((void**)&wvh, g_wvh);
    cudaGetSymbolAddress((void**)&wch, g_wch);

    const int M = BATCH * T_LEN;   // 8192
    const int NX = M * C_DIM;      // 8388608
    const int SMEM = 2 * STAGE_BYTES;   // 37888

    static bool attr_set = false;
    if (!attr_set) {
        cudaFuncSetAttribute(hgemm_pipe,
                             cudaFuncAttributeMaxDynamicSharedMemorySize, SMEM);
        attr_set = true;
    }

    posfeat_kernel<<<1, 512>>>(rpe, Wpos, p_posf);

    // Convert GEMM operands to fp16
    to_half<<<(NX + 255) / 256, 256>>>(x, xh, NX);
    to_half<<<(C_DIM * NH * BD + 255) / 256, 256>>>(Wdisp, wdh, C_DIM * NH * BD);
    to_half<<<(C_DIM * C_DIM + 255) / 256, 256>>>(Wval, wvh, C_DIM * C_DIM);
    to_half<<<(C_DIM * C_DIM + 255) / 256, 256>>>(Wcproj, wch, C_DIM * C_DIM);

    // disp = x @ W_disp  (8192 x 256, K=1024)
    {
        dim3 grid((NH * BD) / BN, M / BM);
        hgemm_pipe<<<grid, 256, SMEM>>>(xh, wdh, p_disp, M, 256, C_DIM);
    }
    // val = x @ W_val    (8192 x 1024, K=1024)
    {
        dim3 grid(C_DIM / BN, M / BM);
        hgemm_pipe<<<grid, 256, SMEM>>>(xh, wvh, p_val, M, C_DIM, C_DIM);
    }
    // strain projections: proj = disp_rows(16) @ Wsf(16x32)
    proj_kernel<<<(BATCH * T_LEN * NH) / 256, 256>>>(p_disp, Wsf, p_proj);

    // windowed attention -> fp16 directly into cproj operand buffer
    {
        const int total = BATCH * NH * T_LEN;   // 131072
        attn_proj<<<(total + 255) / 256, 256>>>(p_proj, p_val, bsf,
                                                wbond, wdmg, bdmg, p_posf, ah);
    }
    // out = attn @ W_cproj (8192 x 1024, K=1024)
    {
        dim3 grid(C_DIM / BN, M / BM);
        hgemm_pipe<<<grid, 256, SMEM>>>(ah, wch, out, M, C_DIM, C_DIM);
    }
}

// round 16
// speedup vs baseline: 5.7675x; 1.8209x over previous
#include <cuda_runtime.h>
#include <cuda_bf16.h>
#include <cuda_fp16.h>
#include <math_constants.h>
#include <mma.h>
#include <cstdint>

using namespace nvcuda;

// Problem constants
#define BATCH 2
#define T_LEN 4096
#define C_DIM 1024
#define NH 16
#define HS 64
#define BD 16
#define DELTA 32

// ---------------------------------------------------------------------------
// Scratch (no allocations allowed)
// ---------------------------------------------------------------------------
__device__ float g_disp[BATCH * T_LEN * (NH * BD)];
__device__ float g_val [BATCH * T_LEN * C_DIM];
__device__ float g_proj[BATCH * T_LEN * NH * 2 * BD];
__device__ float g_posf[DELTA * BD];

__device__ __align__(16) __half g_xh[BATCH * T_LEN * C_DIM];
__device__ __align__(16) __half g_ah[BATCH * T_LEN * C_DIM];
__device__ __align__(16) __half g_wdh[C_DIM * NH * BD];
__device__ __align__(16) __half g_wvh[C_DIM * C_DIM];
__device__ __align__(16) __half g_wch[C_DIM * C_DIM];

// ---------------------------------------------------------------------------
// f32 -> fp16 converts
// ---------------------------------------------------------------------------
__global__ void to_half(const float* __restrict__ in,
                        __half* __restrict__ out, int n)
{
    int i = blockIdx.x * blockDim.x + threadIdx.x;
    if (i >= n) return;
    out[i] = __float2half(in[i]);
}

// vectorized: 4 floats -> 2 half2 per thread (n % 4 == 0)
__global__ void to_half_v4(const float* __restrict__ in,
                           __half* __restrict__ out, int n4)
{
    int i = blockIdx.x * blockDim.x + threadIdx.x;
    if (i >= n4) return;
    float4 v = reinterpret_cast<const float4*>(in)[i];
    __half2* o = reinterpret_cast<__half2*>(out);
    o[2 * i]     = __floats2half2_rn(v.x, v.y);
    o[2 * i + 1] = __floats2half2_rn(v.z, v.w);
}

// ---------------------------------------------------------------------------
// pos_feat = rel_pos_emb (32,16) @ W_pos (16,16)
// ---------------------------------------------------------------------------
__global__ void posfeat_kernel(const float* __restrict__ rpe,
                               const float* __restrict__ Wpos,
                               float* __restrict__ out)
{
    int i = threadIdx.x;
    if (i >= DELTA * BD) return;
    int d = i / BD, k = i % BD;
    float a = 0.f;
    for (int q = 0; q < BD; q++) a += rpe[d * BD + q] * Wpos[q * BD + k];
    out[i] = a;
}

// ---------------------------------------------------------------------------
// proj[r][k] = sum_i disp_row[r][i] * Wsf[i][k]
// ---------------------------------------------------------------------------
__global__ void proj_kernel(const float* __restrict__ disp,
                            const float* __restrict__ Wsf,
                            float* __restrict__ proj)
{
    __shared__ float sW[BD * 2 * BD];
    const int tid = threadIdx.x;
    for (int i = tid; i < BD * 2 * BD; i += 256) sW[i] = Wsf[i];
    __syncthreads();

    const int g = blockIdx.x * 256 + tid;
    if (g >= BATCH * T_LEN * NH) return;

    float xr[BD];
    const float* dr = disp + (size_t)g * BD;
#pragma unroll
    for (int i = 0; i < BD; i += 4) {
        float4 v = *reinterpret_cast<const float4*>(dr + i);
        xr[i] = v.x; xr[i + 1] = v.y; xr[i + 2] = v.z; xr[i + 3] = v.w;
    }

    float* pr = proj + (size_t)g * (2 * BD);
#pragma unroll
    for (int k4 = 0; k4 < 2 * BD; k4 += 4) {
        float a0 = 0.f, a1 = 0.f, a2 = 0.f, a3 = 0.f;
#pragma unroll
        for (int i = 0; i < BD; i++) {
            const float xi = xr[i];
            a0 = fmaf(xi, sW[i * 32 + k4 + 0], a0);
            a1 = fmaf(xi, sW[i * 32 + k4 + 1], a1);
            a2 = fmaf(xi, sW[i * 32 + k4 + 2], a2);
            a3 = fmaf(xi, sW[i * 32 + k4 + 3], a3);
        }
        float4 o = make_float4(a0, a1, a2, a3);
        *reinterpret_cast<float4*>(pr + k4) = o;
    }
}

// ---------------------------------------------------------------------------
// fp16 tensor-core GEMM, BK=64, double-buffered cp.async, FORCED 2 CTAs/SM.
// Per-stage smem:
//   A [128][72] halfs @ 0      (18432 B)  144B row = 9x16B, conflict-free
//   B [64][136] halfs @ 18432  (17408 B)  272B row = 17x16B, conflict-free
//   stage 35840 B, 2 stages = 71680 dynamic smem. 2 CTAs/SM = 143 KB, fits.
// ---------------------------------------------------------------------------
#define BM 128
#define BN 128
#define BK 64
#define LDA 72
#define LDB 136
#define STAGE_BYTES 35840
#define OFF_B 18432

__device__ __forceinline__ void cp_async16(void* smem_ptr, const void* gmem_ptr)
{
    unsigned int s = (unsigned int)__cvta_generic_to_shared(smem_ptr);
    asm volatile("cp.async.cg.shared.global [%0], [%1], 16;" :: "r"(s), "l"(gmem_ptr));
}

__global__ void __launch_bounds__(256, 2) hgemm_pipe(
    const __half* __restrict__ A, const __half* __restrict__ B,
    float* __restrict__ C, int M, int N, int K)
{
    extern __shared__ __align__(16) char dynsmem[];

    const int tid  = threadIdx.x;
    const int warp = tid / 32;
    const int wm   = warp / 2;     // 0..3 -> 32-row strip
    const int wn   = warp % 2;     // 0..1 -> 64-col strip
    const int bm   = blockIdx.y * BM;
    const int bn   = blockIdx.x * BN;

    wmma::fragment<wmma::accumulator, 16, 16, 16, float> acc[2][4];
    for (int i = 0; i < 2; i++)
        for (int j = 0; j < 4; j++)
            wmma::fill_fragment(acc[i][j], 0.f);

    auto prefetch = [&](int s, int k0) {
        char* st = dynsmem + s * STAGE_BYTES;
        __half* pA = reinterpret_cast<__half*>(st);
        __half* pB = reinterpret_cast<__half*>(st + OFF_B);
        // A tile: 128 rows x 64 k halfs = 1024 x 16B chunks, 4 per thread
        for (int l = tid; l < 1024; l += 256) {
            int r  = l >> 3;          // row 0..127
            int c8 = l & 7;           // 8 chunks x 8 halfs = 64 k
            size_t gi = (size_t)(bm + r) * K + k0 + c8 * 8;
            cp_async16(&pA[r * LDA + c8 * 8], &A[gi]);
        }
        // B tile: 64 k-rows x 128 n halfs = 1024 x 16B chunks
        for (int l = tid; l < 1024; l += 256) {
            int r   = l >> 4;         // k row 0..63
            int c16 = l & 15;
            size_t gi = (size_t)(k0 + r) * N + bn + c16 * 8;
            cp_async16(&pB[r * LDB + c16 * 8], &B[gi]);
        }
        asm volatile("cp.async.commit_group;");
    };

    const int nIter = K / BK;     // 16
    prefetch(0, 0);

    for (int it = 0; it < nIter; it++) {
        if (it + 1 < nIter) {
            prefetch((it + 1) & 1, (it + 1) * BK);
            asm volatile("cp.async.wait_group 1;");
        } else {
            asm volatile("cp.async.wait_group 0;");
        }
        __syncthreads();

        char* st = dynsmem + (it & 1) * STAGE_BYTES;
        __half* pA = reinterpret_cast<__half*>(st);
        __half* pB = reinterpret_cast<__half*>(st + OFF_B);

        for (int kk = 0; kk < BK; kk += 16) {
            wmma::fragment<wmma::matrix_a, 16, 16, 16, __half, wmma::row_major> af[2];
            wmma::fragment<wmma::matrix_b, 16, 16, 16, __half, wmma::row_major> bf[4];

            for (int i = 0; i < 2; i++)
                wmma::load_matrix_sync(af[i], &pA[(wm * 32 + i * 16) * LDA + kk], LDA);
            for (int j = 0; j < 4; j++)
                wmma::load_matrix_sync(bf[j], &pB[kk * LDB + wn * 64 + j * 16], LDB);

            for (int i = 0; i < 2; i++)
                for (int j = 0; j < 4; j++)
                    wmma::mma_sync(acc[i][j], af[i], bf[j], acc[i][j]);
        }
        __syncthreads();
    }

    for (int i = 0; i < 2; i++)
        for (int j = 0; j < 4; j++)
            wmma::store_matrix_sync(
                &C[(size_t)(bm + wm * 32 + i * 16) * N + (bn + wn * 64 + j * 16)],
                acc[i][j], N, wmma::mem_row_major);
}

// ---------------------------------------------------------------------------
// Windowed attention (proj form), vectorized output stage, fp16 output.
// Scoring math identical to trusted R15 kernel.
// ---------------------------------------------------------------------------
__device__ __forceinline__ float gelu_ref(float x) {
    return 0.5f * x * (1.f + erff(x * 0.7071067811865476f));
}

__global__ void __launch_bounds__(256) attn_proj(
    const float* __restrict__ proj,   // (B,T,NH,32)
    const float* __restrict__ val,    // (B,T,1024)
    const float* __restrict__ bsf,
    const float* __restrict__ wbond,
    const float* __restrict__ wdmg,
    const float* __restrict__ bdmg,
    const float* __restrict__ posf,
    __half* __restrict__ attn_h)      // (B,T,1024) fp16
{
    __shared__ float cpos[DELTA][BD];
    __shared__ float cdmg[BD];
    __shared__ float swb[BD], swd[BD];

    const int tid = threadIdx.x;
    for (int i = tid; i < DELTA * BD; i += 256)
        cpos[i / BD][i % BD] = bsf[i % BD] + posf[i];
    if (tid < BD) {
        cdmg[tid] = bsf[BD + tid];
        swb[tid] = wbond[tid];
        swd[tid] = wdmg[tid];
    }
    __syncthreads();

    const int g = blockIdx.x * blockDim.x + tid;
    if (g >= BATCH * NH * T_LEN) return;
    const int t  = g % T_LEN;
    const int bn = g / T_LEN;
    const int b  = bn / NH, n = bn % NH;
    const float bdm = bdmg[0];

    float pt[2 * BD];
    const float* ptp = proj + (((size_t)b * T_LEN + t) * NH + n) * (2 * BD);
#pragma unroll
    for (int i = 0; i < 2 * BD; i += 4) {
        float4 v = *reinterpret_cast<const float4*>(ptp + i);
        pt[i] = v.x; pt[i + 1] = v.y; pt[i + 2] = v.z; pt[i + 3] = v.w;
    }

    float score[DELTA];
    for (int d = 0; d < DELTA; d++) {
        const int j = t + d - (DELTA - 1);
        if (j < 0) { score[d] = -CUDART_INF_F; continue; }
        const float* pjp = proj + (((size_t)b * T_LEN + j) * NH + n) * (2 * BD);
        float bond = 0.f, dz = 0.f;
#pragma unroll
        for (int k = 0; k < BD; k++) {
            float fb = pjp[k] - pt[k] + cpos[d][k];
            bond = fmaf(gelu_ref(fb), swb[k], bond);
            float fd = pjp[BD + k] - pt[BD + k] + cdmg[k];
            dz = fmaf(gelu_ref(fd), swd[k], dz);
        }
        const float damage = 1.f / (1.f + expf(-(dz + bdm)));
        score[d] = bond - 10.f * damage;
    }

    float m = -CUDART_INF_F;
    for (int d = 0; d < DELTA; d++) m = fmaxf(m, score[d]);
    float ssum = 0.f;
    for (int d = 0; d < DELTA; d++) { score[d] = expf(score[d] - m); ssum += score[d]; }
    const float inv = 1.f / ssum;
    for (int d = 0; d < DELTA; d++) score[d] *= inv;

    // vectorized output: 4 channels at a time, fp16 stores
    const int d0 = (t >= DELTA - 1) ? 0 : (DELTA - 1 - t);
    const float* vbase = val + ((size_t)b * T_LEN + t - (DELTA - 1)) * C_DIM + n * HS;
    __half* orow = attn_h + ((size_t)b * T_LEN + t) * C_DIM + n * HS;
#pragma unroll 2
    for (int h = 0; h < HS; h += 4) {
        float a0 = 0.f, a1 = 0.f, a2 = 0.f, a3 = 0.f;
        for (int d = d0; d < DELTA; d++) {
            const float w = score[d];
            float4 v = *reinterpret_cast<const float4*>(vbase + (size_t)d * C_DIM + h);
            a0 = fmaf(w, v.x, a0);
            a1 = fmaf(w, v.y, a1);
            a2 = fmaf(w, v.z, a2);
            a3 = fmaf(w, v.w, a3);
        }
        __half2* op = reinterpret_cast<__half2*>(orow + h);
        op[0] = __floats2half2_rn(a0, a1);
        op[1] = __floats2half2_rn(a2, a3);
    }
}

// ---------------------------------------------------------------------------
// Launch
// ---------------------------------------------------------------------------
extern "C" void kernel_launch(void* const* d_in, const int* in_sizes, int n_in,
                              void* d_out, int out_size)
{
    static const int sigA[11] = {8388608, 262144, 1048576, 512, 256, 512, 32, 16, 16, 1, 1048576};

    const float *x = 0, *Wdisp = 0, *Wval = 0, *rpe = 0, *Wpos = 0, *Wsf = 0,
                *bsf = 0, *wbond = 0, *wdmg = 0, *bdmg = 0, *Wcproj = 0;

    bool mA = (n_in == 11);
    for (int i = 0; i < 11 && i < n_in; i++) if (in_sizes[i] != sigA[i]) mA = false;

    if (mA) {
        x      = (const float*)d_in[0];  Wdisp  = (const float*)d_in[1];
        Wval   = (const float*)d_in[2];  rpe    = (const float*)d_in[3];
        Wpos   = (const float*)d_in[4];  Wsf    = (const float*)d_in[5];
        bsf    = (const float*)d_in[6];  wbond  = (const float*)d_in[7];
        wdmg   = (const float*)d_in[8];  bdmg   = (const float*)d_in[9];
        Wcproj = (const float*)d_in[10];
    } else {
        int seen1M = 0, seen512 = 0, seen16 = 0;
        for (int i = 0; i < n_in; i++) {
            const float* p = (const float*)d_in[i];
            switch (in_sizes[i]) {
                case 8388608: x = p; break;
                case 262144:  Wdisp = p; break;
                case 256:     Wpos = p; break;
                case 32:      bsf = p; break;
                case 1:       bdmg = p; break;
                case 1048576: if (seen1M++ == 0) Wval = p; else Wcproj = p; break;
                case 512:     if (seen512++ == 0) rpe = p; else Wsf = p; break;
                case 16:      if (seen16++ == 0) wbond = p; else wdmg = p; break;
                default: break;
            }
        }
    }
    float* out = (float*)d_out;

    float *p_disp, *p_val, *p_proj, *p_posf;
    cudaGetSymbolAddress((void**)&p_disp, g_disp);
    cudaGetSymbolAddress((void**)&p_val,  g_val);
    cudaGetSymbolAddress((void**)&p_proj, g_proj);
    cudaGetSymbolAddress((void**)&p_posf, g_posf);

    __half *xh, *ah, *wdh, *wvh, *wch;
    cudaGetSymbolAddress((void**)&xh,  g_xh);
    cudaGetSymbolAddress((void**)&ah,  g_ah);
    cudaGetSymbolAddress((void**)&wdh, g_wdh);
    cudaGetSymbolAddress((void**)&wvh, g_wvh);
    cudaGetSymbolAddress((void**)&wch, g_wch);

    const int M = BATCH * T_LEN;   // 8192
    const int NX = M * C_DIM;      // 8388608
    const int SMEM = 2 * STAGE_BYTES;   // 71680

    static bool attr_set = false;
    if (!attr_set) {
        cudaFuncSetAttribute(hgemm_pipe,
                             cudaFuncAttributeMaxDynamicSharedMemorySize, SMEM);
        attr_set = true;
    }

    posfeat_kernel<<<1, 512>>>(rpe, Wpos, p_posf);

    // Converts: x vectorized, weights scalar (tiny)
    to_half_v4<<<(NX / 4 + 255) / 256, 256>>>(x, xh, NX / 4);
    to_half<<<(C_DIM * NH * BD + 255) / 256, 256>>>(Wdisp, wdh, C_DIM * NH * BD);
    to_half<<<(C_DIM * C_DIM + 255) / 256, 256>>>(Wval, wvh, C_DIM * C_DIM);
    to_half<<<(C_DIM * C_DIM + 255) / 256, 256>>>(Wcproj, wch, C_DIM * C_DIM);

    // disp = x @ W_disp  (8192 x 256, K=1024)
    {
        dim3 grid((NH * BD) / BN, M / BM);
        hgemm_pipe<<<grid, 256, SMEM>>>(xh, wdh, p_disp, M, 256, C_DIM);
    }
    // val = x @ W_val    (8192 x 1024, K=1024)
    {
        dim3 grid(C_DIM / BN, M / BM);
        hgemm_pipe<<<grid, 256, SMEM>>>(xh, wvh, p_val, M, C_DIM, C_DIM);
    }
    // strain projections
    proj_kernel<<<(BATCH * T_LEN * NH) / 256, 256>>>(p_disp, Wsf, p_proj);

    // windowed attention -> fp16 cproj operand
    {
        const int total = BATCH * NH * T_LEN;
        attn_proj<<<(total + 255) / 256, 256>>>(p_proj, p_val, bsf,
                                                wbond, wdmg, bdmg, p_posf, ah);
    }
    // out = attn @ W_cproj (8192 x 1024, K=1024)
    {
        dim3 grid(C_DIM / BN, M / BM);
        hgemm_pipe<<<grid, 256, SMEM>>>(ah, wch, out, M, C_DIM, C_DIM);
    }
}

// round 17
// speedup vs baseline: 5.7886x; 1.0036x over previous
#include <cuda_runtime.h>
#include <cuda_bf16.h>
#include <cuda_fp16.h>
#include <math_constants.h>
#include <mma.h>
#include <cstdint>

using namespace nvcuda;

// Problem constants
#define BATCH 2
#define T_LEN 4096
#define C_DIM 1024
#define NH 16
#define HS 64
#define BD 16
#define DELTA 32

// ---------------------------------------------------------------------------
// Scratch (no allocations allowed)
// ---------------------------------------------------------------------------
__device__ float g_disp[BATCH * T_LEN * (NH * BD)];
__device__ float g_val [BATCH * T_LEN * C_DIM];
__device__ float g_proj[BATCH * T_LEN * NH * 2 * BD];
__device__ float g_posf[DELTA * BD];

__device__ __align__(16) __half g_xh[BATCH * T_LEN * C_DIM];
__device__ __align__(16) __half g_ah[BATCH * T_LEN * C_DIM];
__device__ __align__(16) __half g_wdh[C_DIM * NH * BD];
__device__ __align__(16) __half g_wvh[C_DIM * C_DIM];
__device__ __align__(16) __half g_wch[C_DIM * C_DIM];

// ---------------------------------------------------------------------------
// f32 -> fp16 converts (vectorized; all sizes here are %4)
// ---------------------------------------------------------------------------
__global__ void to_half_v4(const float* __restrict__ in,
                           __half* __restrict__ out, int n4)
{
    int i = blockIdx.x * blockDim.x + threadIdx.x;
    if (i >= n4) return;
    float4 v = reinterpret_cast<const float4*>(in)[i];
    __half2* o = reinterpret_cast<__half2*>(out);
    o[2 * i]     = __floats2half2_rn(v.x, v.y);
    o[2 * i + 1] = __floats2half2_rn(v.z, v.w);
}

// ---------------------------------------------------------------------------
// pos_feat = rel_pos_emb (32,16) @ W_pos (16,16)
// ---------------------------------------------------------------------------
__global__ void posfeat_kernel(const float* __restrict__ rpe,
                               const float* __restrict__ Wpos,
                               float* __restrict__ out)
{
    int i = threadIdx.x;
    if (i >= DELTA * BD) return;
    int d = i / BD, k = i % BD;
    float a = 0.f;
    for (int q = 0; q < BD; q++) a += rpe[d * BD + q] * Wpos[q * BD + k];
    out[i] = a;
}

// ---------------------------------------------------------------------------
// proj[r][k] = sum_i disp_row[r][i] * Wsf[i][k]
// ---------------------------------------------------------------------------
__global__ void proj_kernel(const float* __restrict__ disp,
                            const float* __restrict__ Wsf,
                            float* __restrict__ proj)
{
    __shared__ float sW[BD * 2 * BD];
    const int tid = threadIdx.x;
    for (int i = tid; i < BD * 2 * BD; i += 256) sW[i] = Wsf[i];
    __syncthreads();

    const int g = blockIdx.x * 256 + tid;
    if (g >= BATCH * T_LEN * NH) return;

    float xr[BD];
    const float* dr = disp + (size_t)g * BD;
#pragma unroll
    for (int i = 0; i < BD; i += 4) {
        float4 v = *reinterpret_cast<const float4*>(dr + i);
        xr[i] = v.x; xr[i + 1] = v.y; xr[i + 2] = v.z; xr[i + 3] = v.w;
    }

    float* pr = proj + (size_t)g * (2 * BD);
#pragma unroll
    for (int k4 = 0; k4 < 2 * BD; k4 += 4) {
        float a0 = 0.f, a1 = 0.f, a2 = 0.f, a3 = 0.f;
#pragma unroll
        for (int i = 0; i < BD; i++) {
            const float xi = xr[i];
            a0 = fmaf(xi, sW[i * 32 + k4 + 0], a0);
            a1 = fmaf(xi, sW[i * 32 + k4 + 1], a1);
            a2 = fmaf(xi, sW[i * 32 + k4 + 2], a2);
            a3 = fmaf(xi, sW[i * 32 + k4 + 3], a3);
        }
        float4 o = make_float4(a0, a1, a2, a3);
        *reinterpret_cast<float4*>(pr + k4) = o;
    }
}

// ---------------------------------------------------------------------------
// fp16 tensor-core GEMM, BK=64, THREE-stage cp.async pipeline, 2 CTAs/SM,
// one barrier per k-iteration.
// Per-stage smem:
//   A [128][72] halfs @ 0      (18432 B)
//   B [64][136] halfs @ 18432  (17408 B)
//   stage 35840 B, 3 stages = 107520 dynamic smem; 2 CTAs = 215 KB <= 228 KB.
// ---------------------------------------------------------------------------
#define BM 128
#define BN 128
#define BK 64
#define LDA 72
#define LDB 136
#define STAGE_BYTES 35840
#define OFF_B 18432
#define NSTAGE 3

__device__ __forceinline__ void cp_async16(void* smem_ptr, const void* gmem_ptr)
{
    unsigned int s = (unsigned int)__cvta_generic_to_shared(smem_ptr);
    asm volatile("cp.async.cg.shared.global [%0], [%1], 16;" :: "r"(s), "l"(gmem_ptr));
}

__global__ void __launch_bounds__(256, 2) hgemm_pipe(
    const __half* __restrict__ A, const __half* __restrict__ B,
    float* __restrict__ C, int M, int N, int K)
{
    extern __shared__ __align__(16) char dynsmem[];

    const int tid  = threadIdx.x;
    const int warp = tid / 32;
    const int wm   = warp / 2;     // 0..3 -> 32-row strip
    const int wn   = warp % 2;     // 0..1 -> 64-col strip
    const int bm   = blockIdx.y * BM;
    const int bn   = blockIdx.x * BN;

    wmma::fragment<wmma::accumulator, 16, 16, 16, float> acc[2][4];
    for (int i = 0; i < 2; i++)
        for (int j = 0; j < 4; j++)
            wmma::fill_fragment(acc[i][j], 0.f);

    auto prefetch = [&](int s, int k0) {
        char* st = dynsmem + s * STAGE_BYTES;
        __half* pA = reinterpret_cast<__half*>(st);
        __half* pB = reinterpret_cast<__half*>(st + OFF_B);
        for (int l = tid; l < 1024; l += 256) {
            int r  = l >> 3;
            int c8 = l & 7;
            size_t gi = (size_t)(bm + r) * K + k0 + c8 * 8;
            cp_async16(&pA[r * LDA + c8 * 8], &A[gi]);
        }
        for (int l = tid; l < 1024; l += 256) {
            int r   = l >> 4;
            int c16 = l & 15;
            size_t gi = (size_t)(k0 + r) * N + bn + c16 * 8;
            cp_async16(&pB[r * LDB + c16 * 8], &B[gi]);
        }
        asm volatile("cp.async.commit_group;");
    };

    const int nIter = K / BK;     // 16
    prefetch(0, 0);
    if (nIter > 1) prefetch(1, BK);

    for (int it = 0; it < nIter; it++) {
        // groups pending: it (must complete), possibly it+1 -> wait <=1
        if (it + 1 < nIter) {
            asm volatile("cp.async.wait_group 1;");
        } else {
            asm volatile("cp.async.wait_group 0;");
        }
        __syncthreads();   // single barrier per iteration (3-stage safety)

        char* st = dynsmem + (it % NSTAGE) * STAGE_BYTES;
        __half* pA = reinterpret_cast<__half*>(st);
        __half* pB = reinterpret_cast<__half*>(st + OFF_B);

        for (int kk = 0; kk < BK; kk += 16) {
            wmma::fragment<wmma::matrix_a, 16, 16, 16, __half, wmma::row_major> af[2];
            wmma::fragment<wmma::matrix_b, 16, 16, 16, __half, wmma::row_major> bf[4];

            for (int i = 0; i < 2; i++)
                wmma::load_matrix_sync(af[i], &pA[(wm * 32 + i * 16) * LDA + kk], LDA);
            for (int j = 0; j < 4; j++)
                wmma::load_matrix_sync(bf[j], &pB[kk * LDB + wn * 64 + j * 16], LDB);

            for (int i = 0; i < 2; i++)
                for (int j = 0; j < 4; j++)
                    wmma::mma_sync(acc[i][j], af[i], bf[j], acc[i][j]);
        }

        // prefetch stage (it+2): targets buffer (it-1)%3, which all warps
        // finished reading before this iteration's barrier.
        if (it + 2 < nIter) prefetch((it + 2) % NSTAGE, (it + 2) * BK);
    }

    for (int i = 0; i < 2; i++)
        for (int j = 0; j < 4; j++)
            wmma::store_matrix_sync(
                &C[(size_t)(bm + wm * 32 + i * 16) * N + (bn + wn * 64 + j * 16)],
                acc[i][j], N, wmma::mem_row_major);
}

// ---------------------------------------------------------------------------
// Windowed attention (proj form), vectorized output stage, fp16 output.
// (BYTE-IDENTICAL to passing R16.)
// ---------------------------------------------------------------------------
__device__ __forceinline__ float gelu_ref(float x) {
    return 0.5f * x * (1.f + erff(x * 0.7071067811865476f));
}

__global__ void __launch_bounds__(256) attn_proj(
    const float* __restrict__ proj,
    const float* __restrict__ val,
    const float* __restrict__ bsf,
    const float* __restrict__ wbond,
    const float* __restrict__ wdmg,
    const float* __restrict__ bdmg,
    const float* __restrict__ posf,
    __half* __restrict__ attn_h)
{
    __shared__ float cpos[DELTA][BD];
    __shared__ float cdmg[BD];
    __shared__ float swb[BD], swd[BD];

    const int tid = threadIdx.x;
    for (int i = tid; i < DELTA * BD; i += 256)
        cpos[i / BD][i % BD] = bsf[i % BD] + posf[i];
    if (tid < BD) {
        cdmg[tid] = bsf[BD + tid];
        swb[tid] = wbond[tid];
        swd[tid] = wdmg[tid];
    }
    __syncthreads();

    const int g = blockIdx.x * blockDim.x + tid;
    if (g >= BATCH * NH * T_LEN) return;
    const int t  = g % T_LEN;
    const int bn = g / T_LEN;
    const int b  = bn / NH, n = bn % NH;
    const float bdm = bdmg[0];

    float pt[2 * BD];
    const float* ptp = proj + (((size_t)b * T_LEN + t) * NH + n) * (2 * BD);
#pragma unroll
    for (int i = 0; i < 2 * BD; i += 4) {
        float4 v = *reinterpret_cast<const float4*>(ptp + i);
        pt[i] = v.x; pt[i + 1] = v.y; pt[i + 2] = v.z; pt[i + 3] = v.w;
    }

    float score[DELTA];
    for (int d = 0; d < DELTA; d++) {
        const int j = t + d - (DELTA - 1);
        if (j < 0) { score[d] = -CUDART_INF_F; continue; }
        const float* pjp = proj + (((size_t)b * T_LEN + j) * NH + n) * (2 * BD);
        float bond = 0.f, dz = 0.f;
#pragma unroll
        for (int k = 0; k < BD; k++) {
            float fb = pjp[k] - pt[k] + cpos[d][k];
            bond = fmaf(gelu_ref(fb), swb[k], bond);
            float fd = pjp[BD + k] - pt[BD + k] + cdmg[k];
            dz = fmaf(gelu_ref(fd), swd[k], dz);
        }
        const float damage = 1.f / (1.f + expf(-(dz + bdm)));
        score[d] = bond - 10.f * damage;
    }

    float m = -CUDART_INF_F;
    for (int d = 0; d < DELTA; d++) m = fmaxf(m, score[d]);
    float ssum = 0.f;
    for (int d = 0; d < DELTA; d++) { score[d] = expf(score[d] - m); ssum += score[d]; }
    const float inv = 1.f / ssum;
    for (int d = 0; d < DELTA; d++) score[d] *= inv;

    const int d0 = (t >= DELTA - 1) ? 0 : (DELTA - 1 - t);
    const float* vbase = val + ((size_t)b * T_LEN + t - (DELTA - 1)) * C_DIM + n * HS;
    __half* orow = attn_h + ((size_t)b * T_LEN + t) * C_DIM + n * HS;
#pragma unroll 2
    for (int h = 0; h < HS; h += 4) {
        float a0 = 0.f, a1 = 0.f, a2 = 0.f, a3 = 0.f;
        for (int d = d0; d < DELTA; d++) {
            const float w = score[d];
            float4 v = *reinterpret_cast<const float4*>(vbase + (size_t)d * C_DIM + h);
            a0 = fmaf(w, v.x, a0);
            a1 = fmaf(w, v.y, a1);
            a2 = fmaf(w, v.z, a2);
            a3 = fmaf(w, v.w, a3);
        }
        __half2* op = reinterpret_cast<__half2*>(orow + h);
        op[0] = __floats2half2_rn(a0, a1);
        op[1] = __floats2half2_rn(a2, a3);
    }
}

// ---------------------------------------------------------------------------
// Launch
// ---------------------------------------------------------------------------
extern "C" void kernel_launch(void* const* d_in, const int* in_sizes, int n_in,
                              void* d_out, int out_size)
{
    static const int sigA[11] = {8388608, 262144, 1048576, 512, 256, 512, 32, 16, 16, 1, 1048576};

    const float *x = 0, *Wdisp = 0, *Wval = 0, *rpe = 0, *Wpos = 0, *Wsf = 0,
                *bsf = 0, *wbond = 0, *wdmg = 0, *bdmg = 0, *Wcproj = 0;

    bool mA = (n_in == 11);
    for (int i = 0; i < 11 && i < n_in; i++) if (in_sizes[i] != sigA[i]) mA = false;

    if (mA) {
        x      = (const float*)d_in[0];  Wdisp  = (const float*)d_in[1];
        Wval   = (const float*)d_in[2];  rpe    = (const float*)d_in[3];
        Wpos   = (const float*)d_in[4];  Wsf    = (const float*)d_in[5];
        bsf    = (const float*)d_in[6];  wbond  = (const float*)d_in[7];
        wdmg   = (const float*)d_in[8];  bdmg   = (const float*)d_in[9];
        Wcproj = (const float*)d_in[10];
    } else {
        int seen1M = 0, seen512 = 0, seen16 = 0;
        for (int i = 0; i < n_in; i++) {
            const float* p = (const float*)d_in[i];
            switch (in_sizes[i]) {
                case 8388608: x = p; break;
                case 262144:  Wdisp = p; break;
                case 256:     Wpos = p; break;
                case 32:      bsf = p; break;
                case 1:       bdmg = p; break;
                case 1048576: if (seen1M++ == 0) Wval = p; else Wcproj = p; break;
                case 512:     if (seen512++ == 0) rpe = p; else Wsf = p; break;
                case 16:      if (seen16++ == 0) wbond = p; else wdmg = p; break;
                default: break;
            }
        }
    }
    float* out = (float*)d_out;

    float *p_disp, *p_val, *p_proj, *p_posf;
    cudaGetSymbolAddress((void**)&p_disp, g_disp);
    cudaGetSymbolAddress((void**)&p_val,  g_val);
    cudaGetSymbolAddress((void**)&p_proj, g_proj);
    cudaGetSymbolAddress((void**)&p_posf, g_posf);

    __half *xh, *ah, *wdh, *wvh, *wch;
    cudaGetSymbolAddress((void**)&xh,  g_xh);
    cudaGetSymbolAddress((void**)&ah,  g_ah);
    cudaGetSymbolAddress((void**)&wdh, g_wdh);
    cudaGetSymbolAddress((void**)&wvh, g_wvh);
    cudaGetSymbolAddress((void**)&wch, g_wch);

    const int M = BATCH * T_LEN;   // 8192
    const int NX = M * C_DIM;      // 8388608
    const int SMEM = NSTAGE * STAGE_BYTES;   // 107520

    static bool attr_set = false;
    if (!attr_set) {
        cudaFuncSetAttribute(hgemm_pipe,
                             cudaFuncAttributeMaxDynamicSharedMemorySize, SMEM);
        attr_set = true;
    }

    posfeat_kernel<<<1, 512>>>(rpe, Wpos, p_posf);

    // Converts (all vectorized)
    to_half_v4<<<(NX / 4 + 255) / 256, 256>>>(x, xh, NX / 4);
    to_half_v4<<<(C_DIM * NH * BD / 4 + 255) / 256, 256>>>(Wdisp, wdh, C_DIM * NH * BD / 4);
    to_half_v4<<<(C_DIM * C_DIM / 4 + 255) / 256, 256>>>(Wval, wvh, C_DIM * C_DIM / 4);
    to_half_v4<<<(C_DIM * C_DIM / 4 + 255) / 256, 256>>>(Wcproj, wch, C_DIM * C_DIM / 4);

    // disp = x @ W_disp  (8192 x 256, K=1024)
    {
        dim3 grid((NH * BD) / BN, M / BM);
        hgemm_pipe<<<grid, 256, SMEM>>>(xh, wdh, p_disp, M, 256, C_DIM);
    }
    // val = x @ W_val    (8192 x 1024, K=1024)
    {
        dim3 grid(C_DIM / BN, M / BM);
        hgemm_pipe<<<grid, 256, SMEM>>>(xh, wvh, p_val, M, C_DIM, C_DIM);
    }
    // strain projections
    proj_kernel<<<(BATCH * T_LEN * NH) / 256, 256>>>(p_disp, Wsf, p_proj);

    // windowed attention -> fp16 cproj operand
    {
        const int total = BATCH * NH * T_LEN;
        attn_proj<<<(total + 255) / 256, 256>>>(p_proj, p_val, bsf,
                                                wbond, wdmg, bdmg, p_posf, ah);
    }
    // out = attn @ W_cproj (8192 x 1024, K=1024)
    {
        dim3 grid(C_DIM / BN, M / BM);
        hgemm_pipe<<<grid, 256, SMEM>>>(ah, wch, out, M, C_DIM, C_DIM);
    }
}